// round 10
// baseline (speedup 1.0000x reference)
#include <cuda_runtime.h>
#include <cuda_bf16.h>
#include <math.h>
#include <stdint.h>

// ---------------------------------------------------------------------------
// Problem constants
// ---------------------------------------------------------------------------
#define NMAX 50000
#define EMAX 800000
#define DDIM 128
#define HEADS 8
#define FIN 256
#define NCLS 40

// Packed-weight arena (uint4 units). Per 128-col block of 16 k: 512 uint4.
#define WP_WI    0
#define WP_L0    8192
#define WPO_Q    0
#define WPO_K    4096
#define WPO_V    8192
#define WPO_O    12288
#define WPO_F1   16384
#define WPO_F2   24576
#define WP_LSTR  32768
#define WP_WOUT  (WP_L0 + 5 * WP_LSTR)
#define WP_TOTAL (WP_WOUT + 4096)

// ---------------------------------------------------------------------------
// Device scratch
// ---------------------------------------------------------------------------
__device__ float g_h  [NMAX * DDIM];
__device__ float g_q  [NMAX * DDIM];
__device__ float g_k  [NMAX * DDIM];
__device__ float g_v  [NMAX * DDIM];
__device__ uint2 g_x2 [NMAX * FIN / 2];
__device__ uint2 g_ln2[NMAX * DDIM / 2];
__device__ uint2 g_ag2[NMAX * DDIM / 2];
__device__ uint2 g_ff2[NMAX * DDIM];
__device__ uint4 g_wp [WP_TOTAL];
__device__ int   g_deg [NMAX];
__device__ int   g_cur [NMAX];
__device__ int   g_off [NMAX + 1];
__device__ int   g_srcs[EMAX];

// ---------------------------------------------------------------------------
// Helpers
// ---------------------------------------------------------------------------
__device__ __forceinline__ unsigned pack_bf2(float a, float b)
{
    __nv_bfloat162 t = __floats2bfloat162_rn(a, b);
    return *reinterpret_cast<unsigned*>(&t);
}

__device__ __forceinline__ uint4 split4(float4 v)
{
    float h0 = __bfloat162float(__float2bfloat16_rn(v.x));
    float h1 = __bfloat162float(__float2bfloat16_rn(v.y));
    float h2 = __bfloat162float(__float2bfloat16_rn(v.z));
    float h3 = __bfloat162float(__float2bfloat16_rn(v.w));
    uint4 u;
    u.x = pack_bf2(h0, h1);
    u.y = pack_bf2(v.x - h0, v.y - h1);
    u.z = pack_bf2(h2, h3);
    u.w = pack_bf2(v.z - h2, v.w - h3);
    return u;
}

__device__ __forceinline__ void mma_bf16(float* d, const uint32_t* a, const uint32_t* b)
{
    asm volatile(
        "mma.sync.aligned.m16n8k16.row.col.f32.bf16.bf16.f32 "
        "{%0,%1,%2,%3}, {%4,%5,%6,%7}, {%8,%9}, {%0,%1,%2,%3};\n"
        : "+f"(d[0]), "+f"(d[1]), "+f"(d[2]), "+f"(d[3])
        : "r"(a[0]), "r"(a[1]), "r"(a[2]), "r"(a[3]), "r"(b[0]), "r"(b[1]));
}

__device__ __forceinline__ void cp_async16(uint32_t saddr, const void* gptr, bool pred)
{
    int bytes = pred ? 16 : 0;
    asm volatile("cp.async.cg.shared.global [%0], [%1], 16, %2;\n"
                 :: "r"(saddr), "l"(gptr), "r"(bytes));
}
#define CP_COMMIT() asm volatile("cp.async.commit_group;\n" ::: "memory")
#define CP_WAIT0()  asm volatile("cp.async.wait_group 0;\n" ::: "memory")

// ---------------------------------------------------------------------------
// Prep kernels
// ---------------------------------------------------------------------------
__global__ void split_x_kernel(const float* __restrict__ src, uint4* __restrict__ dst, int n4)
{
    int t = blockIdx.x * blockDim.x + threadIdx.x;
    if (t >= n4) return;
    dst[t] = split4(((const float4*)src)[t]);
}

__global__ void pack_w_kernel(const float* __restrict__ src, uint4* __restrict__ dst,
                              int K, int Nact, int Npad, int nMat,
                              int srcStride, int dstStride, int dstBase)
{
    long t = (long)blockIdx.x * blockDim.x + threadIdx.x;
    long per = (long)K * Npad / 4;
    if (t >= per * nMat) return;
    int mat = (int)(t / per);
    long r  = t % per;
    int c   = (int)(r & 3);
    long na = r >> 2;
    int nl  = (int)(na & 127);
    int blk = (int)(na >> 7);
    int kb  = blk % (K >> 4);
    int nbk = blk / (K >> 4);
    int n   = nbk * 128 + nl;
    int k0  = kb * 16 + 2 * c;

    const float* W = src + (size_t)mat * srcStride;
    float va = 0.f, vb = 0.f, vc = 0.f, vd = 0.f;
    if (n < Nact) {
        va = W[(size_t)(k0 + 0) * Nact + n];
        vb = W[(size_t)(k0 + 1) * Nact + n];
        vc = W[(size_t)(k0 + 8) * Nact + n];
        vd = W[(size_t)(k0 + 9) * Nact + n];
    }
    float ha = __bfloat162float(__float2bfloat16_rn(va));
    float hb = __bfloat162float(__float2bfloat16_rn(vb));
    float hc = __bfloat162float(__float2bfloat16_rn(vc));
    float hd = __bfloat162float(__float2bfloat16_rn(vd));
    uint4 u;
    u.x = pack_bf2(ha, hb);
    u.y = pack_bf2(hc, hd);
    u.z = pack_bf2(va - ha, vb - hb);
    u.w = pack_bf2(vc - hc, vd - hd);
    dst[(size_t)dstBase + (size_t)mat * dstStride + (size_t)blk * 512 + nl * 4 + c] = u;
}

// ---------------------------------------------------------------------------
// BF16 3-term tensor-core GEMM, cp.async double-buffered, BK=32 (R7 core).
// Optional register-resident fused LayerNorm (requires N==128, gridDim.x==1):
// per-row stats via 2 shfl + one float2 smem slot per (row, warp-half).
// ---------------------------------------------------------------------------
#define BK 32
#define A_STB 160
#define SB_OFF 20480
#define STAGE_BYTES 36864
#define GEMM_SMEM_BYTES (2 * STAGE_BYTES)

template <bool RELU, bool RES, bool SPLIT2, bool FUSELN>
__device__ __forceinline__ void gemm_tc_body(
    const uint2* __restrict__ Ap, const uint4* __restrict__ Bp,
    const float* __restrict__ bias, const float* __restrict__ Rsd,
    float* __restrict__ C, uint2* __restrict__ C2,
    const float* __restrict__ lng, const float* __restrict__ lnb,
    uint2* __restrict__ lnOut,
    int M, int N, int K)
{
    extern __shared__ __align__(16) char smc[];
    __shared__ float2 s_red[2][128];

    const int tid  = threadIdx.x;
    const int lane = tid & 31;
    const int wid  = tid >> 5;
    const int g    = lane >> 2;
    const int c    = lane & 3;
    const int wm   = (wid >> 1) * 32;
    const int wn   = (wid & 1) * 64;

    const int row0 = blockIdx.y * 128;
    const int col0 = blockIdx.x * 128;

    const char* Bbase = (const char*)(Bp + (size_t)blockIdx.x * (K >> 4) * 512);
    const uint32_t smBase = (uint32_t)__cvta_generic_to_shared(smc);

    auto loadTile = [&](int st, int kt) {
        uint32_t sb = smBase + st * STAGE_BYTES;
        #pragma unroll
        for (int i = 0; i < 4; i++) {
            int id = tid + i * 256;
            int r  = id >> 3;
            int ch = id & 7;
            int ar = row0 + r;
            bool ok = ar < M;
            const char* gp = (const char*)Ap
                + ((size_t)(ok ? ar : 0) * (K >> 1) + (size_t)kt * (BK >> 1)) * 8 + ch * 16;
            cp_async16(sb + r * A_STB + ch * 16, gp, ok);
        }
        const char* bp = Bbase + (size_t)kt * 16384;
        #pragma unroll
        for (int i = 0; i < 4; i++) {
            int id = tid + i * 256;
            cp_async16(sb + SB_OFF + id * 16, bp + id * 16, true);
        }
    };

    float acc[2][8][4] = {};

    const int KT = K / BK;
    loadTile(0, 0);
    CP_COMMIT();

    for (int kt = 0; kt < KT; kt++) {
        CP_WAIT0();
        __syncthreads();
        if (kt + 1 < KT) {
            loadTile((kt + 1) & 1, kt + 1);
            CP_COMMIT();
        }

        const char* S = smc + (kt & 1) * STAGE_BYTES;

        #pragma unroll
        for (int kk = 0; kk < 2; kk++) {
            uint32_t aH[2][4], aL[2][4];
            #pragma unroll
            for (int t = 0; t < 2; t++) {
                const char* base = S + (wm + 16 * t + g) * A_STB;
                uint2 w0 = *(const uint2*)(base + (kk * 8 + c) * 8);
                uint2 w1 = *(const uint2*)(base + 8 * A_STB + (kk * 8 + c) * 8);
                uint2 w2 = *(const uint2*)(base + (kk * 8 + c + 4) * 8);
                uint2 w3 = *(const uint2*)(base + 8 * A_STB + (kk * 8 + c + 4) * 8);
                aH[t][0] = w0.x; aL[t][0] = w0.y;
                aH[t][1] = w1.x; aL[t][1] = w1.y;
                aH[t][2] = w2.x; aL[t][2] = w2.y;
                aH[t][3] = w3.x; aL[t][3] = w3.y;
            }
            #pragma unroll
            for (int j = 0; j < 8; j++) {
                int n = wn + 8 * j + g;
                uint4 bb = *(const uint4*)(S + SB_OFF + kk * 8192 + (n * 4 + c) * 16);
                uint32_t bH[2] = {bb.x, bb.y};
                uint32_t bL[2] = {bb.z, bb.w};
                #pragma unroll
                for (int t = 0; t < 2; t++) {
                    float* d = acc[t][j];
                    mma_bf16(d, aH[t], bH);
                    mma_bf16(d, aL[t], bH);
                    mma_bf16(d, aH[t], bL);
                }
            }
        }
        __syncthreads();
    }

    // ---- Epilogue pass 1: finalize values (bias/relu/res), write C/C2,
    //      keep values in acc, accumulate LN partials.
    float psum[2][2], psq[2][2];
    #pragma unroll
    for (int t = 0; t < 2; t++) {
        #pragma unroll
        for (int rr = 0; rr < 2; rr++) {
            psum[t][rr] = 0.f; psq[t][rr] = 0.f;
            int r = row0 + wm + 16 * t + g + rr * 8;
            if (r >= M) continue;
            #pragma unroll
            for (int j = 0; j < 8; j++) {
                int cc = col0 + wn + 8 * j + 2 * c;
                if (cc >= N) continue;
                float v0 = acc[t][j][rr * 2 + 0] + bias[cc];
                float v1 = acc[t][j][rr * 2 + 1] + bias[cc + 1];
                if (RELU) { v0 = fmaxf(v0, 0.f); v1 = fmaxf(v1, 0.f); }
                if (RES) {
                    float2 rv = *(const float2*)(Rsd + (size_t)r * N + cc);
                    v0 += rv.x; v1 += rv.y;
                }
                if (FUSELN) {
                    acc[t][j][rr * 2 + 0] = v0;
                    acc[t][j][rr * 2 + 1] = v1;
                    psum[t][rr] += v0 + v1;
                    psq[t][rr]  += v0 * v0 + v1 * v1;
                }
                if (SPLIT2) {
                    float h0 = __bfloat162float(__float2bfloat16_rn(v0));
                    float h1 = __bfloat162float(__float2bfloat16_rn(v1));
                    uint2 u;
                    u.x = pack_bf2(h0, h1);
                    u.y = pack_bf2(v0 - h0, v1 - h1);
                    C2[(size_t)r * (N >> 1) + (cc >> 1)] = u;
                } else {
                    float2 out; out.x = v0; out.y = v1;
                    *(float2*)(C + (size_t)r * N + cc) = out;
                }
            }
        }
    }

    if (FUSELN) {
        // Reduce over the 4 lanes (c=0..3) sharing each row within the warp.
        #pragma unroll
        for (int t = 0; t < 2; t++)
            #pragma unroll
            for (int rr = 0; rr < 2; rr++) {
                float s  = psum[t][rr];
                float ss = psq[t][rr];
                s  += __shfl_xor_sync(0xffffffffu, s, 1);
                ss += __shfl_xor_sync(0xffffffffu, ss, 1);
                s  += __shfl_xor_sync(0xffffffffu, s, 2);
                ss += __shfl_xor_sync(0xffffffffu, ss, 2);
                if (c == 0) {
                    int rl = wm + 16 * t + g + rr * 8;
                    s_red[wid & 1][rl] = make_float2(s, ss);
                }
            }
        __syncthreads();
        // Pass 2: per-row mu/rstd, apply gamma/beta, write bf16 pairs.
        #pragma unroll
        for (int t = 0; t < 2; t++) {
            #pragma unroll
            for (int rr = 0; rr < 2; rr++) {
                int rl = wm + 16 * t + g + rr * 8;
                int r = row0 + rl;
                if (r >= M) continue;
                float2 p0 = s_red[0][rl];
                float2 p1 = s_red[1][rl];
                float mu  = (p0.x + p1.x) * (1.f / DDIM);
                float var = (p0.y + p1.y) * (1.f / DDIM) - mu * mu;
                float rstd = rsqrtf(var + 1e-5f);
                #pragma unroll
                for (int j = 0; j < 8; j++) {
                    int cc = wn + 8 * j + 2 * c;
                    float2 gv = *(const float2*)(lng + cc);
                    float2 bv = *(const float2*)(lnb + cc);
                    float y0 = (acc[t][j][rr * 2 + 0] - mu) * rstd * gv.x + bv.x;
                    float y1 = (acc[t][j][rr * 2 + 1] - mu) * rstd * gv.y + bv.y;
                    float h0 = __bfloat162float(__float2bfloat16_rn(y0));
                    float h1 = __bfloat162float(__float2bfloat16_rn(y1));
                    uint2 u;
                    u.x = pack_bf2(h0, h1);
                    u.y = pack_bf2(y0 - h0, y1 - h1);
                    lnOut[(size_t)r * 64 + (cc >> 1)] = u;
                }
            }
        }
    }
}

template <bool RELU, bool RES, bool SPLIT2, bool FUSELN>
__global__ __launch_bounds__(256, 2) void gemm_tc_kernel(
    const uint2* __restrict__ Ap, const uint4* __restrict__ Bp,
    const float* __restrict__ bias, const float* __restrict__ Rsd,
    float* __restrict__ C, uint2* __restrict__ C2,
    const float* __restrict__ lng, const float* __restrict__ lnb,
    uint2* __restrict__ lnOut, int M, int N, int K)
{
    gemm_tc_body<RELU, RES, SPLIT2, FUSELN>(Ap, Bp, bias, Rsd, C, C2, lng, lnb, lnOut, M, N, K);
}

__global__ __launch_bounds__(256, 2) void gemm_qkv_kernel(
    const uint2* __restrict__ Ap, const uint4* __restrict__ wp,
    const float* __restrict__ bq, const float* __restrict__ bk, const float* __restrict__ bv,
    float* __restrict__ q, float* __restrict__ k, float* __restrict__ v, int M)
{
    const uint4* Bp; const float* bias; float* C;
    if (blockIdx.z == 0)      { Bp = wp + WPO_Q; bias = bq; C = q; }
    else if (blockIdx.z == 1) { Bp = wp + WPO_K; bias = bk; C = k; }
    else                      { Bp = wp + WPO_V; bias = bv; C = v; }
    gemm_tc_body<false, false, false, false>(Ap, Bp, bias, nullptr, C, nullptr,
                                             nullptr, nullptr, nullptr, M, DDIM, DDIM);
}

// ---------------------------------------------------------------------------
// CSR build (edges grouped by destination)
// ---------------------------------------------------------------------------
__global__ void hist_kernel(const int* __restrict__ dst, int* __restrict__ deg, int E)
{
    int t = blockIdx.x * blockDim.x + threadIdx.x;
    if (t < E) atomicAdd(&deg[dst[t]], 1);
}

__global__ void scan_kernel(const int* __restrict__ deg, int* __restrict__ off, int n)
{
    const int T = 1024;
    __shared__ int sm[T];
    int t = threadIdx.x;
    int chunk = (n + T - 1) / T;
    int b = t * chunk;
    int e = min(n, b + chunk);
    int s = 0;
    for (int i = b; i < e; i++) s += deg[i];
    sm[t] = s;
    __syncthreads();
    for (int o = 1; o < T; o <<= 1) {
        int add = (t >= o) ? sm[t - o] : 0;
        __syncthreads();
        sm[t] += add;
        __syncthreads();
    }
    int excl = (t > 0) ? sm[t - 1] : 0;
    for (int i = b; i < e; i++) { off[i] = excl; excl += deg[i]; }
    if (t == T - 1) off[n] = excl;
}

__global__ void scatter_kernel(const int* __restrict__ src, const int* __restrict__ dst,
                               int* __restrict__ cur, int* __restrict__ srcs, int E)
{
    int t = blockIdx.x * blockDim.x + threadIdx.x;
    if (t < E) {
        int p = atomicAdd(&cur[dst[t]], 1);
        srcs[p] = src[t];
    }
}

// ---------------------------------------------------------------------------
// Fused edge-softmax attention (R7 version) -> bf16 pair output
// ---------------------------------------------------------------------------
__global__ void attn_kernel(const float* __restrict__ q, const float* __restrict__ k,
                            const float* __restrict__ v, const int* __restrict__ off,
                            const int* __restrict__ srcs, uint4* __restrict__ agg2, int n)
{
    int node = blockIdx.x * 8 + threadIdx.y;
    if (node >= n) return;
    int lane = threadIdx.x;

    float4 kf = *(const float4*)(k + (size_t)node * DDIM + lane * 4);
    int beg = off[node], end = off[node + 1];

    float m = -INFINITY, ssum = 0.f;
    float4 acc = make_float4(0.f, 0.f, 0.f, 0.f);

    for (int j = beg; j < end; j++) {
        int s = srcs[j];
        float4 qa = *(const float4*)(q + (size_t)s * DDIM + lane * 4);
        float p = qa.x * kf.x + qa.y * kf.y + qa.z * kf.z + qa.w * kf.w;
        p += __shfl_xor_sync(0xffffffffu, p, 1);
        p += __shfl_xor_sync(0xffffffffu, p, 2);
        p *= 0.25f;  // 1/sqrt(HD=16)

        float mn = fmaxf(m, p);
        float scale = __expf(m - mn);
        float w = __expf(p - mn);
        ssum = ssum * scale + w;

        float4 vv = *(const float4*)(v + (size_t)s * DDIM + lane * 4);
        acc.x = acc.x * scale + w * vv.x;
        acc.y = acc.y * scale + w * vv.y;
        acc.z = acc.z * scale + w * vv.z;
        acc.w = acc.w * scale + w * vv.w;
        m = mn;
    }

    float inv = (end > beg) ? 1.f / ssum : 0.f;
    float4 o;
    o.x = acc.x * inv; o.y = acc.y * inv; o.z = acc.z * inv; o.w = acc.w * inv;
    agg2[(size_t)node * 32 + lane] = split4(o);
}

// ---------------------------------------------------------------------------
// Host orchestration
// ---------------------------------------------------------------------------
extern "C" void kernel_launch(void* const* d_in, const int* in_sizes, int n_in,
                              void* d_out, int out_size)
{
    const float* x    = (const float*)d_in[0];
    const int*   esrc = (const int*)  d_in[1];
    const int*   edst = (const int*)  d_in[2];
    const float* Wi   = (const float*)d_in[3];
    const float* bi   = (const float*)d_in[4];
    const float* Wq   = (const float*)d_in[5];
    const float* bq   = (const float*)d_in[6];
    const float* Wk   = (const float*)d_in[7];
    const float* bk   = (const float*)d_in[8];
    const float* Wv   = (const float*)d_in[9];
    const float* bv   = (const float*)d_in[10];
    const float* Wo   = (const float*)d_in[11];
    const float* bo   = (const float*)d_in[12];
    const float* g1   = (const float*)d_in[13];
    const float* b1   = (const float*)d_in[14];
    const float* Wf1  = (const float*)d_in[15];
    const float* bf1  = (const float*)d_in[16];
    const float* Wf2  = (const float*)d_in[17];
    const float* bf2  = (const float*)d_in[18];
    const float* gout = (const float*)d_in[19];
    const float* boutg= (const float*)d_in[20];
    const float* Wout = (const float*)d_in[21];
    const float* bout = (const float*)d_in[22];

    const int Nn = in_sizes[0] / FIN;   // 50000
    const int Ee = in_sizes[1];         // 800000

    float *h, *q, *k, *v;
    uint2 *x2, *ln2, *ag2, *ff2;
    uint4 *wp;
    int *deg, *cur, *off, *srcs;
    cudaGetSymbolAddress((void**)&h,    g_h);
    cudaGetSymbolAddress((void**)&q,    g_q);
    cudaGetSymbolAddress((void**)&k,    g_k);
    cudaGetSymbolAddress((void**)&v,    g_v);
    cudaGetSymbolAddress((void**)&x2,   g_x2);
    cudaGetSymbolAddress((void**)&ln2,  g_ln2);
    cudaGetSymbolAddress((void**)&ag2,  g_ag2);
    cudaGetSymbolAddress((void**)&ff2,  g_ff2);
    cudaGetSymbolAddress((void**)&wp,   g_wp);
    cudaGetSymbolAddress((void**)&deg,  g_deg);
    cudaGetSymbolAddress((void**)&cur,  g_cur);
    cudaGetSymbolAddress((void**)&off,  g_off);
    cudaGetSymbolAddress((void**)&srcs, g_srcs);

    cudaFuncSetAttribute(gemm_tc_kernel<true,  false, false, true>,  cudaFuncAttributeMaxDynamicSharedMemorySize, GEMM_SMEM_BYTES);
    cudaFuncSetAttribute(gemm_tc_kernel<false, true,  false, true>,  cudaFuncAttributeMaxDynamicSharedMemorySize, GEMM_SMEM_BYTES);
    cudaFuncSetAttribute(gemm_tc_kernel<true,  false, true,  false>, cudaFuncAttributeMaxDynamicSharedMemorySize, GEMM_SMEM_BYTES);
    cudaFuncSetAttribute(gemm_tc_kernel<false, false, false, false>, cudaFuncAttributeMaxDynamicSharedMemorySize, GEMM_SMEM_BYTES);
    cudaFuncSetAttribute(gemm_qkv_kernel,                            cudaFuncAttributeMaxDynamicSharedMemorySize, GEMM_SMEM_BYTES);

    const int mb = (Nn + 127) / 128;
    const dim3 gD(1, mb);
    const dim3 gQKV(1, mb, 3);
    const dim3 gF(2, mb);
    const dim3 gC(1, mb);
    const dim3 warpRows(32, 8);
    const int eBlocks = (Ee + 255) / 256;
    const int nodeBlocks = (Nn + 7) / 8;

    // ---- Prep (once per launch): split x, pack weights
    {
        int n4 = Nn * FIN / 4;
        split_x_kernel<<<(n4 + 255) / 256, 256>>>(x, (uint4*)x2, n4);
        pack_w_kernel<<<(256 * 128 / 4 + 255) / 256, 256>>>(Wi,  wp, 256, 128, 128, 1, 0, 0, WP_WI);
        pack_w_kernel<<<(5 * 128 * 128 / 4 + 255) / 256, 256>>>(Wq, wp, 128, 128, 128, 5, 16384, WP_LSTR, WP_L0 + WPO_Q);
        pack_w_kernel<<<(5 * 128 * 128 / 4 + 255) / 256, 256>>>(Wk, wp, 128, 128, 128, 5, 16384, WP_LSTR, WP_L0 + WPO_K);
        pack_w_kernel<<<(5 * 128 * 128 / 4 + 255) / 256, 256>>>(Wv, wp, 128, 128, 128, 5, 16384, WP_LSTR, WP_L0 + WPO_V);
        pack_w_kernel<<<(5 * 128 * 128 / 4 + 255) / 256, 256>>>(Wo, wp, 128, 128, 128, 5, 16384, WP_LSTR, WP_L0 + WPO_O);
        pack_w_kernel<<<(5 * 128 * 256 / 4 + 255) / 256, 256>>>(Wf1, wp, 128, 256, 256, 5, 32768, WP_LSTR, WP_L0 + WPO_F1);
        pack_w_kernel<<<(5 * 256 * 128 / 4 + 255) / 256, 256>>>(Wf2, wp, 256, 128, 128, 5, 32768, WP_LSTR, WP_L0 + WPO_F2);
        pack_w_kernel<<<(128 * 128 / 4 + 255) / 256, 256>>>(Wout, wp, 128, 40, 128, 1, 0, 0, WP_WOUT);
    }

    // ---- CSR build
    cudaMemsetAsync(deg, 0, Nn * sizeof(int));
    hist_kernel<<<eBlocks, 256>>>(edst, deg, Ee);
    scan_kernel<<<1, 1024>>>(deg, off, Nn);
    cudaMemcpyAsync(cur, off, Nn * sizeof(int), cudaMemcpyDeviceToDevice);
    scatter_kernel<<<eBlocks, 256>>>(esrc, edst, cur, srcs, Ee);

    // h = relu(x @ Wi + bi); fused LN(g1[0]) -> ln2
    gemm_tc_kernel<true, false, false, true><<<gD, 256, GEMM_SMEM_BYTES>>>(
        x2, wp + WP_WI, bi, nullptr, h, nullptr, g1, b1, ln2, Nn, DDIM, FIN);

    for (int i = 0; i < 5; i++) {
        const uint4* wl = wp + WP_L0 + (size_t)i * WP_LSTR;
        const float* lgA = g1 + i * DDIM;      // second norm (reference reuses norms_1)
        const float* lbA = b1 + i * DDIM;
        const float* lgB = (i < 4) ? g1 + (i + 1) * DDIM : gout;   // next layer's first norm
        const float* lbB = (i < 4) ? b1 + (i + 1) * DDIM : boutg;
        // Layer 4's ff2 GEMM writes mid directly into d_out (h no longer needed)
        float* hOut = (i < 4) ? h : (float*)d_out;

        gemm_qkv_kernel<<<gQKV, 256, GEMM_SMEM_BYTES>>>(
            ln2, wl, bq + i * DDIM, bk + i * DDIM, bv + i * DDIM, q, k, v, Nn);

        attn_kernel<<<nodeBlocks, warpRows>>>(q, k, v, off, srcs, (uint4*)ag2, Nn);

        // h += agg @ Wo + bo; fused LN(g1[i]) -> ln2 (feeds FFN)
        gemm_tc_kernel<false, true, false, true><<<gD, 256, GEMM_SMEM_BYTES>>>(
            ag2, wl + WPO_O, bo + i * DDIM, /*Rsd=*/h, /*C=*/h, nullptr, lgA, lbA, ln2,
            Nn, DDIM, DDIM);

        gemm_tc_kernel<true, false, true, false><<<gF, 256, GEMM_SMEM_BYTES>>>(
            ln2, wl + WPO_F1, bf1 + i * 2 * DDIM, nullptr, nullptr, ff2,
            nullptr, nullptr, nullptr, Nn, 2 * DDIM, DDIM);

        // hOut = h + ff @ Wf2 + bf2; fused LN(next) -> ln2
        gemm_tc_kernel<false, true, false, true><<<gD, 256, GEMM_SMEM_BYTES>>>(
            ff2, wl + WPO_F2, bf2 + i * DDIM, /*Rsd=*/h, /*C=*/hOut, nullptr, lgB, lbB, ln2,
            Nn, DDIM, 2 * DDIM);
    }

    // out = LN(h) @ Wout + bout  (LN already fused into last ff2 GEMM; mid already in d_out)
    gemm_tc_kernel<false, false, false, false><<<gC, 256, GEMM_SMEM_BYTES>>>(
        ln2, wp + WP_WOUT, bout, nullptr, (float*)d_out + (size_t)Nn * DDIM, nullptr,
        nullptr, nullptr, nullptr, Nn, NCLS, DDIM);
}

// round 11
// speedup vs baseline: 1.4450x; 1.4450x over previous
#include <cuda_runtime.h>
#include <cuda_bf16.h>
#include <math.h>
#include <stdint.h>

// ---------------------------------------------------------------------------
// Problem constants
// ---------------------------------------------------------------------------
#define NMAX 50000
#define EMAX 800000
#define DDIM 128
#define HEADS 8
#define FIN 256
#define NCLS 40

// Packed-weight arena (uint4 units). Per 128-col block of 16 k: 512 uint4.
#define WP_WI    0
#define WP_L0    8192
#define WPO_Q    0
#define WPO_K    4096
#define WPO_V    8192
#define WPO_O    12288
#define WPO_F1   16384
#define WPO_F2   24576
#define WP_LSTR  32768
#define WP_WOUT  (WP_L0 + 5 * WP_LSTR)
#define WP_TOTAL (WP_WOUT + 4096)

// ---------------------------------------------------------------------------
// Device scratch
// ---------------------------------------------------------------------------
__device__ float g_h  [NMAX * DDIM];
__device__ float g_q  [NMAX * DDIM];
__device__ float g_k  [NMAX * DDIM];
__device__ float g_v  [NMAX * DDIM];
__device__ uint2 g_x2 [NMAX * FIN / 2];
__device__ uint2 g_ln2[NMAX * DDIM / 2];
__device__ uint2 g_ag2[NMAX * DDIM / 2];
__device__ uint2 g_ff2[NMAX * DDIM];
__device__ uint4 g_wp [WP_TOTAL];
__device__ int   g_deg [NMAX];
__device__ int   g_cur [NMAX];
__device__ int   g_off [NMAX + 1];
__device__ int   g_srcs[EMAX];

// ---------------------------------------------------------------------------
// Helpers
// ---------------------------------------------------------------------------
__device__ __forceinline__ unsigned pack_bf2(float a, float b)
{
    __nv_bfloat162 t = __floats2bfloat162_rn(a, b);
    return *reinterpret_cast<unsigned*>(&t);
}

__device__ __forceinline__ uint4 split4(float4 v)
{
    float h0 = __bfloat162float(__float2bfloat16_rn(v.x));
    float h1 = __bfloat162float(__float2bfloat16_rn(v.y));
    float h2 = __bfloat162float(__float2bfloat16_rn(v.z));
    float h3 = __bfloat162float(__float2bfloat16_rn(v.w));
    uint4 u;
    u.x = pack_bf2(h0, h1);
    u.y = pack_bf2(v.x - h0, v.y - h1);
    u.z = pack_bf2(h2, h3);
    u.w = pack_bf2(v.z - h2, v.w - h3);
    return u;
}

__device__ __forceinline__ void mma_bf16(float* d, const uint32_t* a, const uint32_t* b)
{
    asm volatile(
        "mma.sync.aligned.m16n8k16.row.col.f32.bf16.bf16.f32 "
        "{%0,%1,%2,%3}, {%4,%5,%6,%7}, {%8,%9}, {%0,%1,%2,%3};\n"
        : "+f"(d[0]), "+f"(d[1]), "+f"(d[2]), "+f"(d[3])
        : "r"(a[0]), "r"(a[1]), "r"(a[2]), "r"(a[3]), "r"(b[0]), "r"(b[1]));
}

__device__ __forceinline__ void cp_async16(uint32_t saddr, const void* gptr, bool pred)
{
    int bytes = pred ? 16 : 0;
    asm volatile("cp.async.cg.shared.global [%0], [%1], 16, %2;\n"
                 :: "r"(saddr), "l"(gptr), "r"(bytes));
}
#define CP_COMMIT() asm volatile("cp.async.commit_group;\n" ::: "memory")
#define CP_WAIT0()  asm volatile("cp.async.wait_group 0;\n" ::: "memory")

// ---------------------------------------------------------------------------
// Prep: split x into interleaved bf16 pairs
// ---------------------------------------------------------------------------
__global__ void split_x_kernel(const float* __restrict__ src, uint4* __restrict__ dst, int n4)
{
    int t = blockIdx.x * blockDim.x + threadIdx.x;
    if (t >= n4) return;
    dst[t] = split4(((const float4*)src)[t]);
}

// ---------------------------------------------------------------------------
// Prep: pack ALL weights in ONE launch. Thread index == arena uint4 offset;
// the region (matrix, layer) is decoded from the offset ranges.
// ---------------------------------------------------------------------------
__global__ void pack_all_kernel(
    const float* __restrict__ Wi,  const float* __restrict__ Wq,
    const float* __restrict__ Wk,  const float* __restrict__ Wv,
    const float* __restrict__ Wo,  const float* __restrict__ Wf1,
    const float* __restrict__ Wf2, const float* __restrict__ Wout,
    uint4* __restrict__ dst)
{
    int t = blockIdx.x * blockDim.x + threadIdx.x;
    if (t >= WP_TOTAL) return;

    const float* W;
    int K, Nact, li;
    if (t < WP_L0) {                         // Wi: K=256, N=128
        W = Wi; K = 256; Nact = 128; li = t;
    } else if (t < WP_WOUT) {                // per-layer weights
        int r = t - WP_L0;
        int layer = r / WP_LSTR;
        int o = r % WP_LSTR;
        if (o < WPO_F1) {                    // q/k/v/o: K=128, N=128, 4096 each
            int which = o >> 12;
            li = o & 4095;
            K = 128; Nact = 128;
            const float* base = (which == 0) ? Wq : (which == 1) ? Wk
                              : (which == 2) ? Wv : Wo;
            W = base + (size_t)layer * 16384;
        } else if (o < WPO_F2) {             // f1: K=128, N=256
            li = o - WPO_F1; K = 128; Nact = 256;
            W = Wf1 + (size_t)layer * 32768;
        } else {                             // f2: K=256, N=128
            li = o - WPO_F2; K = 256; Nact = 128;
            W = Wf2 + (size_t)layer * 32768;
        }
    } else {                                 // Wout: K=128, Nact=40 (pad 128)
        W = Wout; K = 128; Nact = 40; li = t - WP_WOUT;
    }

    int c   = li & 3;
    int na  = li >> 2;
    int nl  = na & 127;
    int blk = na >> 7;
    int kb  = blk % (K >> 4);
    int nbk = blk / (K >> 4);
    int n   = nbk * 128 + nl;
    int k0  = kb * 16 + 2 * c;

    float va = 0.f, vb = 0.f, vc = 0.f, vd = 0.f;
    if (n < Nact) {
        va = W[(size_t)(k0 + 0) * Nact + n];
        vb = W[(size_t)(k0 + 1) * Nact + n];
        vc = W[(size_t)(k0 + 8) * Nact + n];
        vd = W[(size_t)(k0 + 9) * Nact + n];
    }
    float ha = __bfloat162float(__float2bfloat16_rn(va));
    float hb = __bfloat162float(__float2bfloat16_rn(vb));
    float hc = __bfloat162float(__float2bfloat16_rn(vc));
    float hd = __bfloat162float(__float2bfloat16_rn(vd));
    uint4 u;
    u.x = pack_bf2(ha, hb);
    u.y = pack_bf2(hc, hd);
    u.z = pack_bf2(va - ha, vb - hb);
    u.w = pack_bf2(vc - hc, vd - hd);
    dst[t] = u;
}

// ---------------------------------------------------------------------------
// BF16 3-term tensor-core GEMM, cp.async double-buffered, BK=32 (R7 core).
// A: interleaved bf16 pair rows (uint2 per k-pair). B: packed arena blocks.
// Block 128x128, 8 warps (4M x 2N), warp tile 32x64.
// ---------------------------------------------------------------------------
#define BK 32
#define A_STB 160
#define SB_OFF 20480
#define STAGE_BYTES 36864
#define GEMM_SMEM_BYTES (2 * STAGE_BYTES)

template <bool RELU, bool RES, bool SPLIT2>
__device__ __forceinline__ void gemm_tc_body(
    const uint2* __restrict__ Ap, const uint4* __restrict__ Bp,
    const float* __restrict__ bias, const float* __restrict__ Rsd,
    float* __restrict__ C, uint2* __restrict__ C2,
    int M, int N, int K)
{
    extern __shared__ __align__(16) char smc[];

    const int tid  = threadIdx.x;
    const int lane = tid & 31;
    const int wid  = tid >> 5;
    const int g    = lane >> 2;
    const int c    = lane & 3;
    const int wm   = (wid >> 1) * 32;
    const int wn   = (wid & 1) * 64;

    const int row0 = blockIdx.y * 128;
    const int col0 = blockIdx.x * 128;

    const char* Bbase = (const char*)(Bp + (size_t)blockIdx.x * (K >> 4) * 512);
    const uint32_t smBase = (uint32_t)__cvta_generic_to_shared(smc);

    auto loadTile = [&](int st, int kt) {
        uint32_t sb = smBase + st * STAGE_BYTES;
        #pragma unroll
        for (int i = 0; i < 4; i++) {
            int id = tid + i * 256;
            int r  = id >> 3;
            int ch = id & 7;
            int ar = row0 + r;
            bool ok = ar < M;
            const char* gp = (const char*)Ap
                + ((size_t)(ok ? ar : 0) * (K >> 1) + (size_t)kt * (BK >> 1)) * 8 + ch * 16;
            cp_async16(sb + r * A_STB + ch * 16, gp, ok);
        }
        const char* bp = Bbase + (size_t)kt * 16384;
        #pragma unroll
        for (int i = 0; i < 4; i++) {
            int id = tid + i * 256;
            cp_async16(sb + SB_OFF + id * 16, bp + id * 16, true);
        }
    };

    float acc[2][8][4] = {};

    const int KT = K / BK;
    loadTile(0, 0);
    CP_COMMIT();

    for (int kt = 0; kt < KT; kt++) {
        CP_WAIT0();
        __syncthreads();
        if (kt + 1 < KT) {
            loadTile((kt + 1) & 1, kt + 1);
            CP_COMMIT();
        }

        const char* S = smc + (kt & 1) * STAGE_BYTES;

        #pragma unroll
        for (int kk = 0; kk < 2; kk++) {
            uint32_t aH[2][4], aL[2][4];
            #pragma unroll
            for (int t = 0; t < 2; t++) {
                const char* base = S + (wm + 16 * t + g) * A_STB;
                uint2 w0 = *(const uint2*)(base + (kk * 8 + c) * 8);
                uint2 w1 = *(const uint2*)(base + 8 * A_STB + (kk * 8 + c) * 8);
                uint2 w2 = *(const uint2*)(base + (kk * 8 + c + 4) * 8);
                uint2 w3 = *(const uint2*)(base + 8 * A_STB + (kk * 8 + c + 4) * 8);
                aH[t][0] = w0.x; aL[t][0] = w0.y;
                aH[t][1] = w1.x; aL[t][1] = w1.y;
                aH[t][2] = w2.x; aL[t][2] = w2.y;
                aH[t][3] = w3.x; aL[t][3] = w3.y;
            }
            #pragma unroll
            for (int j = 0; j < 8; j++) {
                int n = wn + 8 * j + g;
                uint4 bb = *(const uint4*)(S + SB_OFF + kk * 8192 + (n * 4 + c) * 16);
                uint32_t bH[2] = {bb.x, bb.y};
                uint32_t bL[2] = {bb.z, bb.w};
                #pragma unroll
                for (int t = 0; t < 2; t++) {
                    float* d = acc[t][j];
                    mma_bf16(d, aH[t], bH);
                    mma_bf16(d, aL[t], bH);
                    mma_bf16(d, aH[t], bL);
                }
            }
        }
        __syncthreads();
    }

    // ---- Epilogue: thread owns rows {wm+16t+g, +8}, cols {wn+8j+2c, +1}
    #pragma unroll
    for (int t = 0; t < 2; t++) {
        #pragma unroll
        for (int rr = 0; rr < 2; rr++) {
            int r = row0 + wm + 16 * t + g + rr * 8;
            if (r >= M) continue;
            #pragma unroll
            for (int j = 0; j < 8; j++) {
                int cc = col0 + wn + 8 * j + 2 * c;
                if (cc >= N) continue;
                float v0 = acc[t][j][rr * 2 + 0] + bias[cc];
                float v1 = acc[t][j][rr * 2 + 1] + bias[cc + 1];
                if (RELU) { v0 = fmaxf(v0, 0.f); v1 = fmaxf(v1, 0.f); }
                if (RES) {
                    float2 rv = *(const float2*)(Rsd + (size_t)r * N + cc);
                    v0 += rv.x; v1 += rv.y;
                }
                if (SPLIT2) {
                    float h0 = __bfloat162float(__float2bfloat16_rn(v0));
                    float h1 = __bfloat162float(__float2bfloat16_rn(v1));
                    uint2 u;
                    u.x = pack_bf2(h0, h1);
                    u.y = pack_bf2(v0 - h0, v1 - h1);
                    C2[(size_t)r * (N >> 1) + (cc >> 1)] = u;
                } else {
                    float2 out; out.x = v0; out.y = v1;
                    *(float2*)(C + (size_t)r * N + cc) = out;
                }
            }
        }
    }
}

template <bool RELU, bool RES, bool SPLIT2>
__global__ __launch_bounds__(256, 2) void gemm_tc_kernel(
    const uint2* __restrict__ Ap, const uint4* __restrict__ Bp,
    const float* __restrict__ bias, const float* __restrict__ Rsd,
    float* __restrict__ C, uint2* __restrict__ C2, int M, int N, int K)
{
    gemm_tc_body<RELU, RES, SPLIT2>(Ap, Bp, bias, Rsd, C, C2, M, N, K);
}

__global__ __launch_bounds__(256, 2) void gemm_qkv_kernel(
    const uint2* __restrict__ Ap, const uint4* __restrict__ wp,
    const float* __restrict__ bq, const float* __restrict__ bk, const float* __restrict__ bv,
    float* __restrict__ q, float* __restrict__ k, float* __restrict__ v, int M)
{
    const uint4* Bp; const float* bias; float* C;
    if (blockIdx.z == 0)      { Bp = wp + WPO_Q; bias = bq; C = q; }
    else if (blockIdx.z == 1) { Bp = wp + WPO_K; bias = bk; C = k; }
    else                      { Bp = wp + WPO_V; bias = bv; C = v; }
    gemm_tc_body<false, false, false>(Ap, Bp, bias, nullptr, C, nullptr, M, DDIM, DDIM);
}

// ---------------------------------------------------------------------------
// LayerNorm over D=128 -> interleaved bf16 pair output (standalone; R7)
// ---------------------------------------------------------------------------
__global__ void ln_kernel(const float* __restrict__ X, const float* __restrict__ g,
                          const float* __restrict__ b, uint4* __restrict__ Y2, int n)
{
    int row = blockIdx.x * 8 + threadIdx.y;
    if (row >= n) return;
    int lane = threadIdx.x;
    float4 x = *(const float4*)(X + (size_t)row * DDIM + lane * 4);
    float s  = x.x + x.y + x.z + x.w;
    float ss = x.x * x.x + x.y * x.y + x.z * x.z + x.w * x.w;
    #pragma unroll
    for (int o = 16; o > 0; o >>= 1) {
        s  += __shfl_xor_sync(0xffffffffu, s, o);
        ss += __shfl_xor_sync(0xffffffffu, ss, o);
    }
    float mu  = s * (1.f / DDIM);
    float var = ss * (1.f / DDIM) - mu * mu;
    float rstd = rsqrtf(var + 1e-5f);
    float4 gv = *(const float4*)(g + lane * 4);
    float4 bv = *(const float4*)(b + lane * 4);
    float4 y;
    y.x = (x.x - mu) * rstd * gv.x + bv.x;
    y.y = (x.y - mu) * rstd * gv.y + bv.y;
    y.z = (x.z - mu) * rstd * gv.z + bv.z;
    y.w = (x.w - mu) * rstd * gv.w + bv.w;
    Y2[(size_t)row * 32 + lane] = split4(y);
}

// ---------------------------------------------------------------------------
// CSR build (edges grouped by destination)
// ---------------------------------------------------------------------------
__global__ void hist_kernel(const int* __restrict__ dst, int* __restrict__ deg, int E)
{
    int t = blockIdx.x * blockDim.x + threadIdx.x;
    if (t < E) atomicAdd(&deg[dst[t]], 1);
}

__global__ void scan_kernel(const int* __restrict__ deg, int* __restrict__ off, int n)
{
    const int T = 1024;
    __shared__ int sm[T];
    int t = threadIdx.x;
    int chunk = (n + T - 1) / T;
    int b = t * chunk;
    int e = min(n, b + chunk);
    int s = 0;
    for (int i = b; i < e; i++) s += deg[i];
    sm[t] = s;
    __syncthreads();
    for (int o = 1; o < T; o <<= 1) {
        int add = (t >= o) ? sm[t - o] : 0;
        __syncthreads();
        sm[t] += add;
        __syncthreads();
    }
    int excl = (t > 0) ? sm[t - 1] : 0;
    for (int i = b; i < e; i++) { off[i] = excl; excl += deg[i]; }
    if (t == T - 1) off[n] = excl;
}

__global__ void scatter_kernel(const int* __restrict__ src, const int* __restrict__ dst,
                               int* __restrict__ cur, int* __restrict__ srcs, int E)
{
    int t = blockIdx.x * blockDim.x + threadIdx.x;
    if (t < E) {
        int p = atomicAdd(&cur[dst[t]], 1);
        srcs[p] = src[t];
    }
}

// ---------------------------------------------------------------------------
// Fused edge-softmax attention with src prefetch -> bf16 pair output
// ---------------------------------------------------------------------------
__global__ void attn_kernel(const float* __restrict__ q, const float* __restrict__ k,
                            const float* __restrict__ v, const int* __restrict__ off,
                            const int* __restrict__ srcs, uint4* __restrict__ agg2, int n)
{
    int node = blockIdx.x * 8 + threadIdx.y;
    if (node >= n) return;
    int lane = threadIdx.x;

    float4 kf = *(const float4*)(k + (size_t)node * DDIM + lane * 4);
    int beg = off[node], end = off[node + 1];

    float m = -INFINITY, ssum = 0.f;
    float4 acc = make_float4(0.f, 0.f, 0.f, 0.f);

    if (beg < end) {
        int s0 = srcs[beg];
        float4 qa = *(const float4*)(q + (size_t)s0 * DDIM + lane * 4);
        float4 va = *(const float4*)(v + (size_t)s0 * DDIM + lane * 4);
        for (int j = beg; j < end; j++) {
            float4 qc = qa, vc = va;
            if (j + 1 < end) {
                int s = srcs[j + 1];
                qa = *(const float4*)(q + (size_t)s * DDIM + lane * 4);
                va = *(const float4*)(v + (size_t)s * DDIM + lane * 4);
            }
            float p = qc.x * kf.x + qc.y * kf.y + qc.z * kf.z + qc.w * kf.w;
            p += __shfl_xor_sync(0xffffffffu, p, 1);
            p += __shfl_xor_sync(0xffffffffu, p, 2);
            p *= 0.25f;  // 1/sqrt(HD=16)

            float mn = fmaxf(m, p);
            float scale = __expf(m - mn);
            float w = __expf(p - mn);
            ssum = ssum * scale + w;

            acc.x = acc.x * scale + w * vc.x;
            acc.y = acc.y * scale + w * vc.y;
            acc.z = acc.z * scale + w * vc.z;
            acc.w = acc.w * scale + w * vc.w;
            m = mn;
        }
    }

    float inv = (end > beg) ? 1.f / ssum : 0.f;
    float4 o;
    o.x = acc.x * inv; o.y = acc.y * inv; o.z = acc.z * inv; o.w = acc.w * inv;
    agg2[(size_t)node * 32 + lane] = split4(o);
}

// ---------------------------------------------------------------------------
// Host orchestration
// ---------------------------------------------------------------------------
extern "C" void kernel_launch(void* const* d_in, const int* in_sizes, int n_in,
                              void* d_out, int out_size)
{
    const float* x    = (const float*)d_in[0];
    const int*   esrc = (const int*)  d_in[1];
    const int*   edst = (const int*)  d_in[2];
    const float* Wi   = (const float*)d_in[3];
    const float* bi   = (const float*)d_in[4];
    const float* Wq   = (const float*)d_in[5];
    const float* bq   = (const float*)d_in[6];
    const float* Wk   = (const float*)d_in[7];
    const float* bk   = (const float*)d_in[8];
    const float* Wv   = (const float*)d_in[9];
    const float* bv   = (const float*)d_in[10];
    const float* Wo   = (const float*)d_in[11];
    const float* bo   = (const float*)d_in[12];
    const float* g1   = (const float*)d_in[13];
    const float* b1   = (const float*)d_in[14];
    const float* Wf1  = (const float*)d_in[15];
    const float* bf1  = (const float*)d_in[16];
    const float* Wf2  = (const float*)d_in[17];
    const float* bf2  = (const float*)d_in[18];
    const float* gout = (const float*)d_in[19];
    const float* boutg= (const float*)d_in[20];
    const float* Wout = (const float*)d_in[21];
    const float* bout = (const float*)d_in[22];

    const int Nn = in_sizes[0] / FIN;   // 50000
    const int Ee = in_sizes[1];         // 800000

    float *h, *q, *k, *v;
    uint2 *x2, *ln2, *ag2, *ff2;
    uint4 *wp;
    int *deg, *cur, *off, *srcs;
    cudaGetSymbolAddress((void**)&h,    g_h);
    cudaGetSymbolAddress((void**)&q,    g_q);
    cudaGetSymbolAddress((void**)&k,    g_k);
    cudaGetSymbolAddress((void**)&v,    g_v);
    cudaGetSymbolAddress((void**)&x2,   g_x2);
    cudaGetSymbolAddress((void**)&ln2,  g_ln2);
    cudaGetSymbolAddress((void**)&ag2,  g_ag2);
    cudaGetSymbolAddress((void**)&ff2,  g_ff2);
    cudaGetSymbolAddress((void**)&wp,   g_wp);
    cudaGetSymbolAddress((void**)&deg,  g_deg);
    cudaGetSymbolAddress((void**)&cur,  g_cur);
    cudaGetSymbolAddress((void**)&off,  g_off);
    cudaGetSymbolAddress((void**)&srcs, g_srcs);

    cudaFuncSetAttribute(gemm_tc_kernel<false, false, false>, cudaFuncAttributeMaxDynamicSharedMemorySize, GEMM_SMEM_BYTES);
    cudaFuncSetAttribute(gemm_tc_kernel<true,  false, false>, cudaFuncAttributeMaxDynamicSharedMemorySize, GEMM_SMEM_BYTES);
    cudaFuncSetAttribute(gemm_tc_kernel<false, true,  false>, cudaFuncAttributeMaxDynamicSharedMemorySize, GEMM_SMEM_BYTES);
    cudaFuncSetAttribute(gemm_tc_kernel<true,  false, true>,  cudaFuncAttributeMaxDynamicSharedMemorySize, GEMM_SMEM_BYTES);
    cudaFuncSetAttribute(gemm_qkv_kernel,                     cudaFuncAttributeMaxDynamicSharedMemorySize, GEMM_SMEM_BYTES);

    const int mb = (Nn + 127) / 128;
    const dim3 gD(1, mb);
    const dim3 gQKV(1, mb, 3);
    const dim3 gF(2, mb);
    const dim3 gC(1, mb);
    const int lnBlocks = (Nn + 7) / 8;
    const dim3 warpRows(32, 8);
    const int eBlocks = (Ee + 255) / 256;
    const int nodeBlocks = (Nn + 7) / 8;

    // ---- Prep (once per launch): split x, pack all weights in ONE launch
    {
        int n4 = Nn * FIN / 4;
        split_x_kernel<<<(n4 + 255) / 256, 256>>>(x, (uint4*)x2, n4);
        pack_all_kernel<<<(WP_TOTAL + 255) / 256, 256>>>(Wi, Wq, Wk, Wv, Wo, Wf1, Wf2, Wout, wp);
    }

    // ---- CSR build
    cudaMemsetAsync(deg, 0, Nn * sizeof(int));
    hist_kernel<<<eBlocks, 256>>>(edst, deg, Ee);
    scan_kernel<<<1, 1024>>>(deg, off, Nn);
    cudaMemcpyAsync(cur, off, Nn * sizeof(int), cudaMemcpyDeviceToDevice);
    scatter_kernel<<<eBlocks, 256>>>(esrc, edst, cur, srcs, Ee);

    // h = relu(x @ Wi + bi)
    gemm_tc_kernel<true, false, false><<<gD, 256, GEMM_SMEM_BYTES>>>(
        x2, wp + WP_WI, bi, nullptr, h, nullptr, Nn, DDIM, FIN);

    for (int i = 0; i < 5; i++) {
        const uint4* wl = wp + WP_L0 + (size_t)i * WP_LSTR;
        // Layer 4's ff2 GEMM writes final h (= mid) directly into d_out.
        float* hOut = (i < 4) ? h : (float*)d_out;

        ln_kernel<<<lnBlocks, warpRows>>>(h, g1 + i * DDIM, b1 + i * DDIM, (uint4*)ln2, Nn);
        gemm_qkv_kernel<<<gQKV, 256, GEMM_SMEM_BYTES>>>(
            ln2, wl, bq + i * DDIM, bk + i * DDIM, bv + i * DDIM, q, k, v, Nn);

        attn_kernel<<<nodeBlocks, warpRows>>>(q, k, v, off, srcs, (uint4*)ag2, Nn);

        // h = h + agg @ Wo + bo   (bias, Rsd, C order)
        gemm_tc_kernel<false, true, false><<<gD, 256, GEMM_SMEM_BYTES>>>(
            ag2, wl + WPO_O, bo + i * DDIM, /*Rsd=*/h, /*C=*/h, nullptr, Nn, DDIM, DDIM);

        ln_kernel<<<lnBlocks, warpRows>>>(h, g1 + i * DDIM, b1 + i * DDIM, (uint4*)ln2, Nn);
        gemm_tc_kernel<true, false, true><<<gF, 256, GEMM_SMEM_BYTES>>>(
            ln2, wl + WPO_F1, bf1 + i * 2 * DDIM, nullptr, nullptr, ff2, Nn, 2 * DDIM, DDIM);

        // hOut = h + ff @ Wf2 + bf2  (Rsd=h reads old h; C=hOut writes h or d_out)
        gemm_tc_kernel<false, true, false><<<gD, 256, GEMM_SMEM_BYTES>>>(
            ff2, wl + WPO_F2, bf2 + i * DDIM, /*Rsd=*/h, /*C=*/hOut, nullptr, Nn, DDIM, 2 * DDIM);
    }

    // mid already sits in d_out[0 : Nn*DDIM]. Final LN reads it from there.
    ln_kernel<<<lnBlocks, warpRows>>>((const float*)d_out, gout, boutg, (uint4*)ln2, Nn);
    gemm_tc_kernel<false, false, false><<<gC, 256, GEMM_SMEM_BYTES>>>(
        ln2, wp + WP_WOUT, bout, nullptr, (float*)d_out + (size_t)Nn * DDIM, nullptr,
        Nn, NCLS, DDIM);
}

// round 12
// speedup vs baseline: 1.5505x; 1.0730x over previous
#include <cuda_runtime.h>
#include <cuda_bf16.h>
#include <math.h>
#include <stdint.h>

// ---------------------------------------------------------------------------
// Problem constants
// ---------------------------------------------------------------------------
#define NMAX 50000
#define EMAX 800000
#define DDIM 128
#define HEADS 8
#define FIN 256
#define NCLS 40

// Packed-weight arena (uint4 units). Per 128-col block of 16 k: 512 uint4.
#define WP_WI    0
#define WP_L0    8192
#define WPO_Q    0
#define WPO_K    4096
#define WPO_V    8192
#define WPO_O    12288
#define WPO_F1   16384
#define WPO_F2   24576
#define WP_LSTR  32768
#define WP_WOUT  (WP_L0 + 5 * WP_LSTR)
#define WP_TOTAL (WP_WOUT + 4096)

// ---------------------------------------------------------------------------
// Device scratch
// ---------------------------------------------------------------------------
__device__ float g_h  [NMAX * DDIM];
__device__ float g_q  [NMAX * DDIM];
__device__ float g_k  [NMAX * DDIM];
__device__ float g_v  [NMAX * DDIM];
__device__ uint2 g_x2 [NMAX * FIN / 2];
__device__ uint2 g_ln2[NMAX * DDIM / 2];
__device__ uint2 g_ag2[NMAX * DDIM / 2];
__device__ uint2 g_ff2[NMAX * DDIM];
__device__ uint4 g_wp [WP_TOTAL];
__device__ int   g_deg [NMAX];
__device__ int   g_cur [NMAX];
__device__ int   g_off [NMAX + 1];
__device__ int   g_bsum[256];
__device__ int   g_srcs[EMAX];

// ---------------------------------------------------------------------------
// Helpers
// ---------------------------------------------------------------------------
__device__ __forceinline__ unsigned pack_bf2(float a, float b)
{
    __nv_bfloat162 t = __floats2bfloat162_rn(a, b);
    return *reinterpret_cast<unsigned*>(&t);
}

__device__ __forceinline__ uint4 split4(float4 v)
{
    float h0 = __bfloat162float(__float2bfloat16_rn(v.x));
    float h1 = __bfloat162float(__float2bfloat16_rn(v.y));
    float h2 = __bfloat162float(__float2bfloat16_rn(v.z));
    float h3 = __bfloat162float(__float2bfloat16_rn(v.w));
    uint4 u;
    u.x = pack_bf2(h0, h1);
    u.y = pack_bf2(v.x - h0, v.y - h1);
    u.z = pack_bf2(h2, h3);
    u.w = pack_bf2(v.z - h2, v.w - h3);
    return u;
}

__device__ __forceinline__ void mma_bf16(float* d, const uint32_t* a, const uint32_t* b)
{
    asm volatile(
        "mma.sync.aligned.m16n8k16.row.col.f32.bf16.bf16.f32 "
        "{%0,%1,%2,%3}, {%4,%5,%6,%7}, {%8,%9}, {%0,%1,%2,%3};\n"
        : "+f"(d[0]), "+f"(d[1]), "+f"(d[2]), "+f"(d[3])
        : "r"(a[0]), "r"(a[1]), "r"(a[2]), "r"(a[3]), "r"(b[0]), "r"(b[1]));
}

__device__ __forceinline__ void cp_async16(uint32_t saddr, const void* gptr, bool pred)
{
    int bytes = pred ? 16 : 0;
    asm volatile("cp.async.cg.shared.global [%0], [%1], 16, %2;\n"
                 :: "r"(saddr), "l"(gptr), "r"(bytes));
}
#define CP_COMMIT() asm volatile("cp.async.commit_group;\n" ::: "memory")
#define CP_WAIT0()  asm volatile("cp.async.wait_group 0;\n" ::: "memory")

// ---------------------------------------------------------------------------
// Prep: split x into interleaved bf16 pairs
// ---------------------------------------------------------------------------
__global__ void split_x_kernel(const float* __restrict__ src, uint4* __restrict__ dst, int n4)
{
    int t = blockIdx.x * blockDim.x + threadIdx.x;
    if (t >= n4) return;
    dst[t] = split4(((const float4*)src)[t]);
}

// ---------------------------------------------------------------------------
// Prep: pack ALL weights in ONE launch (arena offset == thread index)
// ---------------------------------------------------------------------------
__global__ void pack_all_kernel(
    const float* __restrict__ Wi,  const float* __restrict__ Wq,
    const float* __restrict__ Wk,  const float* __restrict__ Wv,
    const float* __restrict__ Wo,  const float* __restrict__ Wf1,
    const float* __restrict__ Wf2, const float* __restrict__ Wout,
    uint4* __restrict__ dst)
{
    int t = blockIdx.x * blockDim.x + threadIdx.x;
    if (t >= WP_TOTAL) return;

    const float* W;
    int K, Nact, li;
    if (t < WP_L0) {
        W = Wi; K = 256; Nact = 128; li = t;
    } else if (t < WP_WOUT) {
        int r = t - WP_L0;
        int layer = r / WP_LSTR;
        int o = r % WP_LSTR;
        if (o < WPO_F1) {
            int which = o >> 12;
            li = o & 4095;
            K = 128; Nact = 128;
            const float* base = (which == 0) ? Wq : (which == 1) ? Wk
                              : (which == 2) ? Wv : Wo;
            W = base + (size_t)layer * 16384;
        } else if (o < WPO_F2) {
            li = o - WPO_F1; K = 128; Nact = 256;
            W = Wf1 + (size_t)layer * 32768;
        } else {
            li = o - WPO_F2; K = 256; Nact = 128;
            W = Wf2 + (size_t)layer * 32768;
        }
    } else {
        W = Wout; K = 128; Nact = 40; li = t - WP_WOUT;
    }

    int c   = li & 3;
    int na  = li >> 2;
    int nl  = na & 127;
    int blk = na >> 7;
    int kb  = blk % (K >> 4);
    int nbk = blk / (K >> 4);
    int n   = nbk * 128 + nl;
    int k0  = kb * 16 + 2 * c;

    float va = 0.f, vb = 0.f, vc = 0.f, vd = 0.f;
    if (n < Nact) {
        va = W[(size_t)(k0 + 0) * Nact + n];
        vb = W[(size_t)(k0 + 1) * Nact + n];
        vc = W[(size_t)(k0 + 8) * Nact + n];
        vd = W[(size_t)(k0 + 9) * Nact + n];
    }
    float ha = __bfloat162float(__float2bfloat16_rn(va));
    float hb = __bfloat162float(__float2bfloat16_rn(vb));
    float hc = __bfloat162float(__float2bfloat16_rn(vc));
    float hd = __bfloat162float(__float2bfloat16_rn(vd));
    uint4 u;
    u.x = pack_bf2(ha, hb);
    u.y = pack_bf2(hc, hd);
    u.z = pack_bf2(va - ha, vb - hb);
    u.w = pack_bf2(vc - hc, vd - hd);
    dst[t] = u;
}

// ---------------------------------------------------------------------------
// BF16 3-term tensor-core GEMM, cp.async double-buffered, BK=32.
// Template MT: 2 -> 128-row block (warp tile 32x64), 1 -> 64-row block (16x64).
// ---------------------------------------------------------------------------
#define BK 32
#define A_STB 160
#define GEMM_SMEM(MT) (2 * ((MT) * 64 * A_STB + 16384))

template <bool RELU, bool RES, bool SPLIT2, int MT>
__device__ __forceinline__ void gemm_tc_body(
    const uint2* __restrict__ Ap, const uint4* __restrict__ Bp,
    const float* __restrict__ bias, const float* __restrict__ Rsd,
    float* __restrict__ C, uint2* __restrict__ C2,
    int M, int N, int K)
{
    extern __shared__ __align__(16) char smc[];

    constexpr int ROWS  = MT * 64;
    constexpr int SBOFF = ROWS * A_STB;
    constexpr int STB   = SBOFF + 16384;

    const int tid  = threadIdx.x;
    const int lane = tid & 31;
    const int wid  = tid >> 5;
    const int g    = lane >> 2;
    const int c    = lane & 3;
    const int wm   = (wid >> 1) * (MT * 16);
    const int wn   = (wid & 1) * 64;

    const int row0 = blockIdx.y * ROWS;
    const int col0 = blockIdx.x * 128;

    const char* Bbase = (const char*)(Bp + (size_t)blockIdx.x * (K >> 4) * 512);
    const uint32_t smBase = (uint32_t)__cvta_generic_to_shared(smc);

    auto loadTile = [&](int st, int kt) {
        uint32_t sb = smBase + st * STB;
        #pragma unroll
        for (int i = 0; i < ROWS / 32; i++) {
            int id = tid + i * 256;
            int r  = id >> 3;
            int ch = id & 7;
            int ar = row0 + r;
            bool ok = ar < M;
            const char* gp = (const char*)Ap
                + ((size_t)(ok ? ar : 0) * (K >> 1) + (size_t)kt * (BK >> 1)) * 8 + ch * 16;
            cp_async16(sb + r * A_STB + ch * 16, gp, ok);
        }
        const char* bp = Bbase + (size_t)kt * 16384;
        #pragma unroll
        for (int i = 0; i < 4; i++) {
            int id = tid + i * 256;
            cp_async16(sb + SBOFF + id * 16, bp + id * 16, true);
        }
    };

    float acc[MT][8][4] = {};

    const int KT = K / BK;
    loadTile(0, 0);
    CP_COMMIT();

    for (int kt = 0; kt < KT; kt++) {
        CP_WAIT0();
        __syncthreads();
        if (kt + 1 < KT) {
            loadTile((kt + 1) & 1, kt + 1);
            CP_COMMIT();
        }

        const char* S = smc + (kt & 1) * STB;

        #pragma unroll
        for (int kk = 0; kk < 2; kk++) {
            uint32_t aH[MT][4], aL[MT][4];
            #pragma unroll
            for (int t = 0; t < MT; t++) {
                const char* base = S + (wm + 16 * t + g) * A_STB;
                uint2 w0 = *(const uint2*)(base + (kk * 8 + c) * 8);
                uint2 w1 = *(const uint2*)(base + 8 * A_STB + (kk * 8 + c) * 8);
                uint2 w2 = *(const uint2*)(base + (kk * 8 + c + 4) * 8);
                uint2 w3 = *(const uint2*)(base + 8 * A_STB + (kk * 8 + c + 4) * 8);
                aH[t][0] = w0.x; aL[t][0] = w0.y;
                aH[t][1] = w1.x; aL[t][1] = w1.y;
                aH[t][2] = w2.x; aL[t][2] = w2.y;
                aH[t][3] = w3.x; aL[t][3] = w3.y;
            }
            #pragma unroll
            for (int j = 0; j < 8; j++) {
                int n = wn + 8 * j + g;
                uint4 bb = *(const uint4*)(S + SBOFF + kk * 8192 + (n * 4 + c) * 16);
                uint32_t bH[2] = {bb.x, bb.y};
                uint32_t bL[2] = {bb.z, bb.w};
                #pragma unroll
                for (int t = 0; t < MT; t++) {
                    float* d = acc[t][j];
                    mma_bf16(d, aH[t], bH);
                    mma_bf16(d, aL[t], bH);
                    mma_bf16(d, aH[t], bL);
                }
            }
        }
        __syncthreads();
    }

    // ---- Epilogue: thread owns rows {wm+16t+g, +8}, cols {wn+8j+2c, +1}
    #pragma unroll
    for (int t = 0; t < MT; t++) {
        #pragma unroll
        for (int rr = 0; rr < 2; rr++) {
            int r = row0 + wm + 16 * t + g + rr * 8;
            if (r >= M) continue;
            #pragma unroll
            for (int j = 0; j < 8; j++) {
                int cc = col0 + wn + 8 * j + 2 * c;
                if (cc >= N) continue;
                float v0 = acc[t][j][rr * 2 + 0] + bias[cc];
                float v1 = acc[t][j][rr * 2 + 1] + bias[cc + 1];
                if (RELU) { v0 = fmaxf(v0, 0.f); v1 = fmaxf(v1, 0.f); }
                if (RES) {
                    float2 rv = *(const float2*)(Rsd + (size_t)r * N + cc);
                    v0 += rv.x; v1 += rv.y;
                }
                if (SPLIT2) {
                    float h0 = __bfloat162float(__float2bfloat16_rn(v0));
                    float h1 = __bfloat162float(__float2bfloat16_rn(v1));
                    uint2 u;
                    u.x = pack_bf2(h0, h1);
                    u.y = pack_bf2(v0 - h0, v1 - h1);
                    C2[(size_t)r * (N >> 1) + (cc >> 1)] = u;
                } else {
                    float2 out; out.x = v0; out.y = v1;
                    *(float2*)(C + (size_t)r * N + cc) = out;
                }
            }
        }
    }
}

template <bool RELU, bool RES, bool SPLIT2, int MT>
__global__ __launch_bounds__(256, 2) void gemm_tc_kernel(
    const uint2* __restrict__ Ap, const uint4* __restrict__ Bp,
    const float* __restrict__ bias, const float* __restrict__ Rsd,
    float* __restrict__ C, uint2* __restrict__ C2, int M, int N, int K)
{
    gemm_tc_body<RELU, RES, SPLIT2, MT>(Ap, Bp, bias, Rsd, C, C2, M, N, K);
}

__global__ __launch_bounds__(256, 2) void gemm_qkv_kernel(
    const uint2* __restrict__ Ap, const uint4* __restrict__ wp,
    const float* __restrict__ bq, const float* __restrict__ bk, const float* __restrict__ bv,
    float* __restrict__ q, float* __restrict__ k, float* __restrict__ v, int M)
{
    const uint4* Bp; const float* bias; float* C;
    if (blockIdx.z == 0)      { Bp = wp + WPO_Q; bias = bq; C = q; }
    else if (blockIdx.z == 1) { Bp = wp + WPO_K; bias = bk; C = k; }
    else                      { Bp = wp + WPO_V; bias = bv; C = v; }
    gemm_tc_body<false, false, false, 2>(Ap, Bp, bias, nullptr, C, nullptr, M, DDIM, DDIM);
}

// ---------------------------------------------------------------------------
// LayerNorm over D=128 -> interleaved bf16 pair output
// ---------------------------------------------------------------------------
__global__ void ln_kernel(const float* __restrict__ X, const float* __restrict__ g,
                          const float* __restrict__ b, uint4* __restrict__ Y2, int n)
{
    int row = blockIdx.x * 8 + threadIdx.y;
    if (row >= n) return;
    int lane = threadIdx.x;
    float4 x = *(const float4*)(X + (size_t)row * DDIM + lane * 4);
    float s  = x.x + x.y + x.z + x.w;
    float ss = x.x * x.x + x.y * x.y + x.z * x.z + x.w * x.w;
    #pragma unroll
    for (int o = 16; o > 0; o >>= 1) {
        s  += __shfl_xor_sync(0xffffffffu, s, o);
        ss += __shfl_xor_sync(0xffffffffu, ss, o);
    }
    float mu  = s * (1.f / DDIM);
    float var = ss * (1.f / DDIM) - mu * mu;
    float rstd = rsqrtf(var + 1e-5f);
    float4 gv = *(const float4*)(g + lane * 4);
    float4 bv = *(const float4*)(b + lane * 4);
    float4 y;
    y.x = (x.x - mu) * rstd * gv.x + bv.x;
    y.y = (x.y - mu) * rstd * gv.y + bv.y;
    y.z = (x.z - mu) * rstd * gv.z + bv.z;
    y.w = (x.w - mu) * rstd * gv.w + bv.w;
    Y2[(size_t)row * 32 + lane] = split4(y);
}

// ---------------------------------------------------------------------------
// CSR build: histogram + 3-phase scan + scatter
// ---------------------------------------------------------------------------
__global__ void hist_kernel(const int* __restrict__ dst, int* __restrict__ deg, int E)
{
    int t = blockIdx.x * blockDim.x + threadIdx.x;
    if (t < E) atomicAdd(&deg[dst[t]], 1);
}

// Phase 1: per-block (512 elems) sums
__global__ void scan_part_kernel(const int* __restrict__ deg, int* __restrict__ bsum, int n)
{
    __shared__ int ws[16];
    int t = threadIdx.x;
    int i = blockIdx.x * 512 + t;
    int v = (i < n) ? deg[i] : 0;
    #pragma unroll
    for (int o = 16; o > 0; o >>= 1) v += __shfl_xor_sync(0xffffffffu, v, o);
    if ((t & 31) == 0) ws[t >> 5] = v;
    __syncthreads();
    if (t == 0) {
        int s = 0;
        #pragma unroll
        for (int w = 0; w < 16; w++) s += ws[w];
        bsum[blockIdx.x] = s;
    }
}

// Phase 2: single-block exclusive scan of nb (<=128) partials; writes off[n]=total
__global__ void scan_top_kernel(int* __restrict__ bsum, int* __restrict__ off, int n, int nb)
{
    __shared__ int sm[128];
    int t = threadIdx.x;
    int v = (t < nb) ? bsum[t] : 0;
    sm[t] = v;
    __syncthreads();
    #pragma unroll
    for (int o = 1; o < 128; o <<= 1) {
        int a = (t >= o) ? sm[t - o] : 0;
        __syncthreads();
        sm[t] += a;
        __syncthreads();
    }
    if (t < nb) bsum[t] = sm[t] - v;   // exclusive block offset
    if (t == 0) off[n] = sm[nb - 1];   // total (nb>=1; sm already inclusive)
}

// Phase 3: per-block local scan + block offset; writes off AND cur
__global__ void scan_apply_kernel(const int* __restrict__ deg, const int* __restrict__ bsum,
                                  int* __restrict__ off, int* __restrict__ cur, int n)
{
    __shared__ int sm[512];
    int t = threadIdx.x;
    int i = blockIdx.x * 512 + t;
    int v = (i < n) ? deg[i] : 0;
    sm[t] = v;
    __syncthreads();
    #pragma unroll
    for (int o = 1; o < 512; o <<= 1) {
        int a = (t >= o) ? sm[t - o] : 0;
        __syncthreads();
        sm[t] += a;
        __syncthreads();
    }
    if (i < n) {
        int excl = sm[t] - v + bsum[blockIdx.x];
        off[i] = excl;
        cur[i] = excl;
    }
}

__global__ void scatter_kernel(const int* __restrict__ src, const int* __restrict__ dst,
                               int* __restrict__ cur, int* __restrict__ srcs, int E)
{
    int t = blockIdx.x * blockDim.x + threadIdx.x;
    if (t < E) {
        int p = atomicAdd(&cur[dst[t]], 1);
        srcs[p] = src[t];
    }
}

// ---------------------------------------------------------------------------
// Fused edge-softmax attention with src prefetch -> bf16 pair output
// ---------------------------------------------------------------------------
__global__ void attn_kernel(const float* __restrict__ q, const float* __restrict__ k,
                            const float* __restrict__ v, const int* __restrict__ off,
                            const int* __restrict__ srcs, uint4* __restrict__ agg2, int n)
{
    int node = blockIdx.x * 8 + threadIdx.y;
    if (node >= n) return;
    int lane = threadIdx.x;

    float4 kf = *(const float4*)(k + (size_t)node * DDIM + lane * 4);
    int beg = off[node], end = off[node + 1];

    float m = -INFINITY, ssum = 0.f;
    float4 acc = make_float4(0.f, 0.f, 0.f, 0.f);

    if (beg < end) {
        int s0 = srcs[beg];
        float4 qa = *(const float4*)(q + (size_t)s0 * DDIM + lane * 4);
        float4 va = *(const float4*)(v + (size_t)s0 * DDIM + lane * 4);
        for (int j = beg; j < end; j++) {
            float4 qc = qa, vc = va;
            if (j + 1 < end) {
                int s = srcs[j + 1];
                qa = *(const float4*)(q + (size_t)s * DDIM + lane * 4);
                va = *(const float4*)(v + (size_t)s * DDIM + lane * 4);
            }
            float p = qc.x * kf.x + qc.y * kf.y + qc.z * kf.z + qc.w * kf.w;
            p += __shfl_xor_sync(0xffffffffu, p, 1);
            p += __shfl_xor_sync(0xffffffffu, p, 2);
            p *= 0.25f;  // 1/sqrt(HD=16)

            float mn = fmaxf(m, p);
            float scale = __expf(m - mn);
            float w = __expf(p - mn);
            ssum = ssum * scale + w;

            acc.x = acc.x * scale + w * vc.x;
            acc.y = acc.y * scale + w * vc.y;
            acc.z = acc.z * scale + w * vc.z;
            acc.w = acc.w * scale + w * vc.w;
            m = mn;
        }
    }

    float inv = (end > beg) ? 1.f / ssum : 0.f;
    float4 o;
    o.x = acc.x * inv; o.y = acc.y * inv; o.z = acc.z * inv; o.w = acc.w * inv;
    agg2[(size_t)node * 32 + lane] = split4(o);
}

// ---------------------------------------------------------------------------
// Host orchestration
// ---------------------------------------------------------------------------
extern "C" void kernel_launch(void* const* d_in, const int* in_sizes, int n_in,
                              void* d_out, int out_size)
{
    const float* x    = (const float*)d_in[0];
    const int*   esrc = (const int*)  d_in[1];
    const int*   edst = (const int*)  d_in[2];
    const float* Wi   = (const float*)d_in[3];
    const float* bi   = (const float*)d_in[4];
    const float* Wq   = (const float*)d_in[5];
    const float* bq   = (const float*)d_in[6];
    const float* Wk   = (const float*)d_in[7];
    const float* bk   = (const float*)d_in[8];
    const float* Wv   = (const float*)d_in[9];
    const float* bv   = (const float*)d_in[10];
    const float* Wo   = (const float*)d_in[11];
    const float* bo   = (const float*)d_in[12];
    const float* g1   = (const float*)d_in[13];
    const float* b1   = (const float*)d_in[14];
    const float* Wf1  = (const float*)d_in[15];
    const float* bf1  = (const float*)d_in[16];
    const float* Wf2  = (const float*)d_in[17];
    const float* bf2  = (const float*)d_in[18];
    const float* gout = (const float*)d_in[19];
    const float* boutg= (const float*)d_in[20];
    const float* Wout = (const float*)d_in[21];
    const float* bout = (const float*)d_in[22];

    const int Nn = in_sizes[0] / FIN;   // 50000
    const int Ee = in_sizes[1];         // 800000

    float *h, *q, *k, *v;
    uint2 *x2, *ln2, *ag2, *ff2;
    uint4 *wp;
    int *deg, *cur, *off, *bsum, *srcs;
    cudaGetSymbolAddress((void**)&h,    g_h);
    cudaGetSymbolAddress((void**)&q,    g_q);
    cudaGetSymbolAddress((void**)&k,    g_k);
    cudaGetSymbolAddress((void**)&v,    g_v);
    cudaGetSymbolAddress((void**)&x2,   g_x2);
    cudaGetSymbolAddress((void**)&ln2,  g_ln2);
    cudaGetSymbolAddress((void**)&ag2,  g_ag2);
    cudaGetSymbolAddress((void**)&ff2,  g_ff2);
    cudaGetSymbolAddress((void**)&wp,   g_wp);
    cudaGetSymbolAddress((void**)&deg,  g_deg);
    cudaGetSymbolAddress((void**)&cur,  g_cur);
    cudaGetSymbolAddress((void**)&off,  g_off);
    cudaGetSymbolAddress((void**)&bsum, g_bsum);
    cudaGetSymbolAddress((void**)&srcs, g_srcs);

    cudaFuncSetAttribute(gemm_tc_kernel<true,  false, false, 1>, cudaFuncAttributeMaxDynamicSharedMemorySize, GEMM_SMEM(1));
    cudaFuncSetAttribute(gemm_tc_kernel<false, true,  false, 1>, cudaFuncAttributeMaxDynamicSharedMemorySize, GEMM_SMEM(1));
    cudaFuncSetAttribute(gemm_tc_kernel<false, false, false, 1>, cudaFuncAttributeMaxDynamicSharedMemorySize, GEMM_SMEM(1));
    cudaFuncSetAttribute(gemm_tc_kernel<true,  false, true,  2>, cudaFuncAttributeMaxDynamicSharedMemorySize, GEMM_SMEM(2));
    cudaFuncSetAttribute(gemm_qkv_kernel,                        cudaFuncAttributeMaxDynamicSharedMemorySize, GEMM_SMEM(2));

    const int mb1 = (Nn + 63) / 64;      // 64-row-tile grids
    const int mb2 = (Nn + 127) / 128;    // 128-row-tile grids
    const dim3 gD(1, mb1);               // D-output GEMMs (MT=1)
    const dim3 gQKV(1, mb2, 3);
    const dim3 gF(2, mb2);               // ff1 (MT=2)
    const dim3 gC(1, mb1);               // classifier (MT=1)
    const int lnBlocks = (Nn + 7) / 8;
    const dim3 warpRows(32, 8);
    const int eBlocks = (Ee + 255) / 256;
    const int nodeBlocks = (Nn + 7) / 8;
    const int nbScan = (Nn + 511) / 512; // 98

    // ---- Prep (once per launch)
    {
        int n4 = Nn * FIN / 4;
        split_x_kernel<<<(n4 + 255) / 256, 256>>>(x, (uint4*)x2, n4);
        pack_all_kernel<<<(WP_TOTAL + 255) / 256, 256>>>(Wi, Wq, Wk, Wv, Wo, Wf1, Wf2, Wout, wp);
    }

    // ---- CSR build (3-phase scan; scan_apply also initializes cur)
    cudaMemsetAsync(deg, 0, Nn * sizeof(int));
    hist_kernel<<<eBlocks, 256>>>(edst, deg, Ee);
    scan_part_kernel<<<nbScan, 512>>>(deg, bsum, Nn);
    scan_top_kernel<<<1, 128>>>(bsum, off, Nn, nbScan);
    scan_apply_kernel<<<nbScan, 512>>>(deg, bsum, off, cur, Nn);
    scatter_kernel<<<eBlocks, 256>>>(esrc, edst, cur, srcs, Ee);

    // h = relu(x @ Wi + bi)
    gemm_tc_kernel<true, false, false, 1><<<gD, 256, GEMM_SMEM(1)>>>(
        x2, wp + WP_WI, bi, nullptr, h, nullptr, Nn, DDIM, FIN);

    for (int i = 0; i < 5; i++) {
        const uint4* wl = wp + WP_L0 + (size_t)i * WP_LSTR;
        // Layer 4's ff2 GEMM writes final h (= mid) directly into d_out.
        float* hOut = (i < 4) ? h : (float*)d_out;

        ln_kernel<<<lnBlocks, warpRows>>>(h, g1 + i * DDIM, b1 + i * DDIM, (uint4*)ln2, Nn);
        gemm_qkv_kernel<<<gQKV, 256, GEMM_SMEM(2)>>>(
            ln2, wl, bq + i * DDIM, bk + i * DDIM, bv + i * DDIM, q, k, v, Nn);

        attn_kernel<<<nodeBlocks, warpRows>>>(q, k, v, off, srcs, (uint4*)ag2, Nn);

        // h = h + agg @ Wo + bo   (bias, Rsd, C order)
        gemm_tc_kernel<false, true, false, 1><<<gD, 256, GEMM_SMEM(1)>>>(
            ag2, wl + WPO_O, bo + i * DDIM, /*Rsd=*/h, /*C=*/h, nullptr, Nn, DDIM, DDIM);

        ln_kernel<<<lnBlocks, warpRows>>>(h, g1 + i * DDIM, b1 + i * DDIM, (uint4*)ln2, Nn);
        gemm_tc_kernel<true, false, true, 2><<<gF, 256, GEMM_SMEM(2)>>>(
            ln2, wl + WPO_F1, bf1 + i * 2 * DDIM, nullptr, nullptr, ff2, Nn, 2 * DDIM, DDIM);

        // hOut = h + ff @ Wf2 + bf2
        gemm_tc_kernel<false, true, false, 1><<<gD, 256, GEMM_SMEM(1)>>>(
            ff2, wl + WPO_F2, bf2 + i * DDIM, /*Rsd=*/h, /*C=*/hOut, nullptr, Nn, DDIM, 2 * DDIM);
    }

    // mid already sits in d_out[0 : Nn*DDIM]. Final LN reads it from there.
    ln_kernel<<<lnBlocks, warpRows>>>((const float*)d_out, gout, boutg, (uint4*)ln2, Nn);
    gemm_tc_kernel<false, false, false, 1><<<gC, 256, GEMM_SMEM(1)>>>(
        ln2, wp + WP_WOUT, bout, nullptr, (float*)d_out + (size_t)Nn * DDIM, nullptr,
        Nn, NCLS, DDIM);
}

// round 13
// speedup vs baseline: 1.6402x; 1.0578x over previous
#include <cuda_runtime.h>
#include <cuda_bf16.h>
#include <cuda_fp16.h>
#include <math.h>
#include <stdint.h>

// ---------------------------------------------------------------------------
// Problem constants
// ---------------------------------------------------------------------------
#define NMAX 50000
#define EMAX 800000
#define DDIM 128
#define HEADS 8
#define FIN 256
#define NCLS 40

// Packed-weight arena (uint4 units). Per 128-col block of 16 k: 512 uint4.
#define WP_WI    0
#define WP_L0    8192
#define WPO_Q    0
#define WPO_K    4096
#define WPO_V    8192
#define WPO_O    12288
#define WPO_F1   16384
#define WPO_F2   24576
#define WP_LSTR  32768
#define WP_WOUT  (WP_L0 + 5 * WP_LSTR)
#define WP_TOTAL (WP_WOUT + 4096)

// ---------------------------------------------------------------------------
// Device scratch
// ---------------------------------------------------------------------------
__device__ float  g_h  [NMAX * DDIM];
__device__ __half g_qh [NMAX * DDIM];
__device__ float  g_k  [NMAX * DDIM];
__device__ __half g_vh [NMAX * DDIM];
__device__ uint2  g_x2 [NMAX * FIN / 2];
__device__ uint2  g_ln2[NMAX * DDIM / 2];
__device__ uint2  g_ag2[NMAX * DDIM / 2];
__device__ uint2  g_ff2[NMAX * DDIM];
__device__ uint4  g_wp [WP_TOTAL];
__device__ int    g_deg [NMAX];
__device__ int    g_cur [NMAX];
__device__ int    g_off [NMAX + 1];
__device__ int    g_bsum[256];
__device__ int    g_srcs[EMAX];

// ---------------------------------------------------------------------------
// Helpers
// ---------------------------------------------------------------------------
__device__ __forceinline__ unsigned pack_bf2(float a, float b)
{
    __nv_bfloat162 t = __floats2bfloat162_rn(a, b);
    return *reinterpret_cast<unsigned*>(&t);
}

__device__ __forceinline__ uint4 split4(float4 v)
{
    float h0 = __bfloat162float(__float2bfloat16_rn(v.x));
    float h1 = __bfloat162float(__float2bfloat16_rn(v.y));
    float h2 = __bfloat162float(__float2bfloat16_rn(v.z));
    float h3 = __bfloat162float(__float2bfloat16_rn(v.w));
    uint4 u;
    u.x = pack_bf2(h0, h1);
    u.y = pack_bf2(v.x - h0, v.y - h1);
    u.z = pack_bf2(h2, h3);
    u.w = pack_bf2(v.z - h2, v.w - h3);
    return u;
}

__device__ __forceinline__ void mma_bf16(float* d, const uint32_t* a, const uint32_t* b)
{
    asm volatile(
        "mma.sync.aligned.m16n8k16.row.col.f32.bf16.bf16.f32 "
        "{%0,%1,%2,%3}, {%4,%5,%6,%7}, {%8,%9}, {%0,%1,%2,%3};\n"
        : "+f"(d[0]), "+f"(d[1]), "+f"(d[2]), "+f"(d[3])
        : "r"(a[0]), "r"(a[1]), "r"(a[2]), "r"(a[3]), "r"(b[0]), "r"(b[1]));
}

__device__ __forceinline__ void cp_async16(uint32_t saddr, const void* gptr, bool pred)
{
    int bytes = pred ? 16 : 0;
    asm volatile("cp.async.cg.shared.global [%0], [%1], 16, %2;\n"
                 :: "r"(saddr), "l"(gptr), "r"(bytes));
}
#define CP_COMMIT() asm volatile("cp.async.commit_group;\n" ::: "memory")
#define CP_WAIT1()  asm volatile("cp.async.wait_group 1;\n" ::: "memory")

// ---------------------------------------------------------------------------
// Prep: split x into interleaved bf16 pairs
// ---------------------------------------------------------------------------
__global__ void split_x_kernel(const float* __restrict__ src, uint4* __restrict__ dst, int n4)
{
    int t = blockIdx.x * blockDim.x + threadIdx.x;
    if (t >= n4) return;
    dst[t] = split4(((const float4*)src)[t]);
}

// ---------------------------------------------------------------------------
// Prep: pack ALL weights in ONE launch (arena offset == thread index)
// ---------------------------------------------------------------------------
__global__ void pack_all_kernel(
    const float* __restrict__ Wi,  const float* __restrict__ Wq,
    const float* __restrict__ Wk,  const float* __restrict__ Wv,
    const float* __restrict__ Wo,  const float* __restrict__ Wf1,
    const float* __restrict__ Wf2, const float* __restrict__ Wout,
    uint4* __restrict__ dst)
{
    int t = blockIdx.x * blockDim.x + threadIdx.x;
    if (t >= WP_TOTAL) return;

    const float* W;
    int K, Nact, li;
    if (t < WP_L0) {
        W = Wi; K = 256; Nact = 128; li = t;
    } else if (t < WP_WOUT) {
        int r = t - WP_L0;
        int layer = r / WP_LSTR;
        int o = r % WP_LSTR;
        if (o < WPO_F1) {
            int which = o >> 12;
            li = o & 4095;
            K = 128; Nact = 128;
            const float* base = (which == 0) ? Wq : (which == 1) ? Wk
                              : (which == 2) ? Wv : Wo;
            W = base + (size_t)layer * 16384;
        } else if (o < WPO_F2) {
            li = o - WPO_F1; K = 128; Nact = 256;
            W = Wf1 + (size_t)layer * 32768;
        } else {
            li = o - WPO_F2; K = 256; Nact = 128;
            W = Wf2 + (size_t)layer * 32768;
        }
    } else {
        W = Wout; K = 128; Nact = 40; li = t - WP_WOUT;
    }

    int c   = li & 3;
    int na  = li >> 2;
    int nl  = na & 127;
    int blk = na >> 7;
    int kb  = blk % (K >> 4);
    int nbk = blk / (K >> 4);
    int n   = nbk * 128 + nl;
    int k0  = kb * 16 + 2 * c;

    float va = 0.f, vb = 0.f, vc = 0.f, vd = 0.f;
    if (n < Nact) {
        va = W[(size_t)(k0 + 0) * Nact + n];
        vb = W[(size_t)(k0 + 1) * Nact + n];
        vc = W[(size_t)(k0 + 8) * Nact + n];
        vd = W[(size_t)(k0 + 9) * Nact + n];
    }
    float ha = __bfloat162float(__float2bfloat16_rn(va));
    float hb = __bfloat162float(__float2bfloat16_rn(vb));
    float hc = __bfloat162float(__float2bfloat16_rn(vc));
    float hd = __bfloat162float(__float2bfloat16_rn(vd));
    uint4 u;
    u.x = pack_bf2(ha, hb);
    u.y = pack_bf2(hc, hd);
    u.z = pack_bf2(va - ha, vb - hb);
    u.w = pack_bf2(vc - hc, vd - hd);
    dst[t] = u;
}

// ---------------------------------------------------------------------------
// BF16 3-term tensor-core GEMM, cp.async 3-stage pipeline, BK=32.
// MT: 2 -> 128-row block (warp tile 32x64), 1 -> 64-row block (16x64).
// OUTM: 0 = fp32, 1 = bf16-pair (C2), 2 = fp16 (C reinterpreted as __half*).
// ---------------------------------------------------------------------------
#define BK 32
#define A_STB 160
#define NSTAGE 3
#define GEMM_SMEM(MT) (NSTAGE * ((MT) * 64 * A_STB + 16384))

template <bool RELU, bool RES, int OUTM, int MT>
__device__ __forceinline__ void gemm_tc_body(
    const uint2* __restrict__ Ap, const uint4* __restrict__ Bp,
    const float* __restrict__ bias, const float* __restrict__ Rsd,
    float* __restrict__ C, uint2* __restrict__ C2,
    int M, int N, int K)
{
    extern __shared__ __align__(16) char smc[];

    constexpr int ROWS  = MT * 64;
    constexpr int SBOFF = ROWS * A_STB;
    constexpr int STB   = SBOFF + 16384;

    const int tid  = threadIdx.x;
    const int lane = tid & 31;
    const int wid  = tid >> 5;
    const int g    = lane >> 2;
    const int c    = lane & 3;
    const int wm   = (wid >> 1) * (MT * 16);
    const int wn   = (wid & 1) * 64;

    const int row0 = blockIdx.y * ROWS;
    const int col0 = blockIdx.x * 128;

    const char* Bbase = (const char*)(Bp + (size_t)blockIdx.x * (K >> 4) * 512);
    const uint32_t smBase = (uint32_t)__cvta_generic_to_shared(smc);

    auto loadTile = [&](int st, int kt) {
        uint32_t sb = smBase + st * STB;
        #pragma unroll
        for (int i = 0; i < ROWS / 32; i++) {
            int id = tid + i * 256;
            int r  = id >> 3;
            int ch = id & 7;
            int ar = row0 + r;
            bool ok = ar < M;
            const char* gp = (const char*)Ap
                + ((size_t)(ok ? ar : 0) * (K >> 1) + (size_t)kt * (BK >> 1)) * 8 + ch * 16;
            cp_async16(sb + r * A_STB + ch * 16, gp, ok);
        }
        const char* bp = Bbase + (size_t)kt * 16384;
        #pragma unroll
        for (int i = 0; i < 4; i++) {
            int id = tid + i * 256;
            cp_async16(sb + SBOFF + id * 16, bp + id * 16, true);
        }
    };

    float acc[MT][8][4] = {};

    const int KT = K / BK;   // >= 4 for all our shapes
    loadTile(0, 0);
    CP_COMMIT();
    loadTile(1, 1);
    CP_COMMIT();

    for (int kt = 0; kt < KT; kt++) {
        CP_WAIT1();
        __syncthreads();

        const char* S = smc + (kt % NSTAGE) * STB;

        #pragma unroll
        for (int kk = 0; kk < 2; kk++) {
            uint32_t aH[MT][4], aL[MT][4];
            #pragma unroll
            for (int t = 0; t < MT; t++) {
                const char* base = S + (wm + 16 * t + g) * A_STB;
                uint2 w0 = *(const uint2*)(base + (kk * 8 + c) * 8);
                uint2 w1 = *(const uint2*)(base + 8 * A_STB + (kk * 8 + c) * 8);
                uint2 w2 = *(const uint2*)(base + (kk * 8 + c + 4) * 8);
                uint2 w3 = *(const uint2*)(base + 8 * A_STB + (kk * 8 + c + 4) * 8);
                aH[t][0] = w0.x; aL[t][0] = w0.y;
                aH[t][1] = w1.x; aL[t][1] = w1.y;
                aH[t][2] = w2.x; aL[t][2] = w2.y;
                aH[t][3] = w3.x; aL[t][3] = w3.y;
            }
            #pragma unroll
            for (int j = 0; j < 8; j++) {
                int n = wn + 8 * j + g;
                uint4 bb = *(const uint4*)(S + SBOFF + kk * 8192 + (n * 4 + c) * 16);
                uint32_t bH[2] = {bb.x, bb.y};
                uint32_t bL[2] = {bb.z, bb.w};
                #pragma unroll
                for (int t = 0; t < MT; t++) {
                    float* d = acc[t][j];
                    mma_bf16(d, aH[t], bH);
                    mma_bf16(d, aL[t], bH);
                    mma_bf16(d, aH[t], bL);
                }
            }
        }
        // Prefetch tile kt+2 into the stage used at iteration kt-1 (all warps
        // passed the barrier above, so it is free). Always commit to keep the
        // group count aligned with CP_WAIT1.
        if (kt + 2 < KT) loadTile((kt + 2) % NSTAGE, kt + 2);
        CP_COMMIT();
    }

    // ---- Epilogue: thread owns rows {wm+16t+g, +8}, cols {wn+8j+2c, +1}
    #pragma unroll
    for (int t = 0; t < MT; t++) {
        #pragma unroll
        for (int rr = 0; rr < 2; rr++) {
            int r = row0 + wm + 16 * t + g + rr * 8;
            if (r >= M) continue;
            #pragma unroll
            for (int j = 0; j < 8; j++) {
                int cc = col0 + wn + 8 * j + 2 * c;
                if (cc >= N) continue;
                float v0 = acc[t][j][rr * 2 + 0] + bias[cc];
                float v1 = acc[t][j][rr * 2 + 1] + bias[cc + 1];
                if (RELU) { v0 = fmaxf(v0, 0.f); v1 = fmaxf(v1, 0.f); }
                if (RES) {
                    float2 rv = *(const float2*)(Rsd + (size_t)r * N + cc);
                    v0 += rv.x; v1 += rv.y;
                }
                if (OUTM == 1) {
                    float h0 = __bfloat162float(__float2bfloat16_rn(v0));
                    float h1 = __bfloat162float(__float2bfloat16_rn(v1));
                    uint2 u;
                    u.x = pack_bf2(h0, h1);
                    u.y = pack_bf2(v0 - h0, v1 - h1);
                    C2[(size_t)r * (N >> 1) + (cc >> 1)] = u;
                } else if (OUTM == 2) {
                    __half2 hv = __floats2half2_rn(v0, v1);
                    *(__half2*)((__half*)C + (size_t)r * N + cc) = hv;
                } else {
                    float2 out; out.x = v0; out.y = v1;
                    *(float2*)(C + (size_t)r * N + cc) = out;
                }
            }
        }
    }
}

template <bool RELU, bool RES, int OUTM, int MT>
__global__ __launch_bounds__(256, 2) void gemm_tc_kernel(
    const uint2* __restrict__ Ap, const uint4* __restrict__ Bp,
    const float* __restrict__ bias, const float* __restrict__ Rsd,
    float* __restrict__ C, uint2* __restrict__ C2, int M, int N, int K)
{
    gemm_tc_body<RELU, RES, OUTM, MT>(Ap, Bp, bias, Rsd, C, C2, M, N, K);
}

// q,v written as fp16; k as fp32
__global__ __launch_bounds__(256, 2) void gemm_qkv_kernel(
    const uint2* __restrict__ Ap, const uint4* __restrict__ wp,
    const float* __restrict__ bq, const float* __restrict__ bk, const float* __restrict__ bv,
    __half* __restrict__ qh, float* __restrict__ k, __half* __restrict__ vh, int M)
{
    if (blockIdx.z == 0)
        gemm_tc_body<false, false, 2, 2>(Ap, wp + WPO_Q, bq, nullptr, (float*)qh, nullptr, M, DDIM, DDIM);
    else if (blockIdx.z == 1)
        gemm_tc_body<false, false, 0, 2>(Ap, wp + WPO_K, bk, nullptr, k, nullptr, M, DDIM, DDIM);
    else
        gemm_tc_body<false, false, 2, 2>(Ap, wp + WPO_V, bv, nullptr, (float*)vh, nullptr, M, DDIM, DDIM);
}

// ---------------------------------------------------------------------------
// LayerNorm over D=128 -> interleaved bf16 pair output
// ---------------------------------------------------------------------------
__global__ void ln_kernel(const float* __restrict__ X, const float* __restrict__ g,
                          const float* __restrict__ b, uint4* __restrict__ Y2, int n)
{
    int row = blockIdx.x * 8 + threadIdx.y;
    if (row >= n) return;
    int lane = threadIdx.x;
    float4 x = *(const float4*)(X + (size_t)row * DDIM + lane * 4);
    float s  = x.x + x.y + x.z + x.w;
    float ss = x.x * x.x + x.y * x.y + x.z * x.z + x.w * x.w;
    #pragma unroll
    for (int o = 16; o > 0; o >>= 1) {
        s  += __shfl_xor_sync(0xffffffffu, s, o);
        ss += __shfl_xor_sync(0xffffffffu, ss, o);
    }
    float mu  = s * (1.f / DDIM);
    float var = ss * (1.f / DDIM) - mu * mu;
    float rstd = rsqrtf(var + 1e-5f);
    float4 gv = *(const float4*)(g + lane * 4);
    float4 bv = *(const float4*)(b + lane * 4);
    float4 y;
    y.x = (x.x - mu) * rstd * gv.x + bv.x;
    y.y = (x.y - mu) * rstd * gv.y + bv.y;
    y.z = (x.z - mu) * rstd * gv.z + bv.z;
    y.w = (x.w - mu) * rstd * gv.w + bv.w;
    Y2[(size_t)row * 32 + lane] = split4(y);
}

// ---------------------------------------------------------------------------
// CSR build: histogram + 3-phase scan + scatter
// ---------------------------------------------------------------------------
__global__ void hist_kernel(const int* __restrict__ dst, int* __restrict__ deg, int E)
{
    int t = blockIdx.x * blockDim.x + threadIdx.x;
    if (t < E) atomicAdd(&deg[dst[t]], 1);
}

__global__ void scan_part_kernel(const int* __restrict__ deg, int* __restrict__ bsum, int n)
{
    __shared__ int ws[16];
    int t = threadIdx.x;
    int i = blockIdx.x * 512 + t;
    int v = (i < n) ? deg[i] : 0;
    #pragma unroll
    for (int o = 16; o > 0; o >>= 1) v += __shfl_xor_sync(0xffffffffu, v, o);
    if ((t & 31) == 0) ws[t >> 5] = v;
    __syncthreads();
    if (t == 0) {
        int s = 0;
        #pragma unroll
        for (int w = 0; w < 16; w++) s += ws[w];
        bsum[blockIdx.x] = s;
    }
}

__global__ void scan_top_kernel(int* __restrict__ bsum, int* __restrict__ off, int n, int nb)
{
    __shared__ int sm[128];
    int t = threadIdx.x;
    int v = (t < nb) ? bsum[t] : 0;
    sm[t] = v;
    __syncthreads();
    #pragma unroll
    for (int o = 1; o < 128; o <<= 1) {
        int a = (t >= o) ? sm[t - o] : 0;
        __syncthreads();
        sm[t] += a;
        __syncthreads();
    }
    if (t < nb) bsum[t] = sm[t] - v;
    if (t == 0) off[n] = sm[nb - 1];
}

__global__ void scan_apply_kernel(const int* __restrict__ deg, const int* __restrict__ bsum,
                                  int* __restrict__ off, int* __restrict__ cur, int n)
{
    __shared__ int sm[512];
    int t = threadIdx.x;
    int i = blockIdx.x * 512 + t;
    int v = (i < n) ? deg[i] : 0;
    sm[t] = v;
    __syncthreads();
    #pragma unroll
    for (int o = 1; o < 512; o <<= 1) {
        int a = (t >= o) ? sm[t - o] : 0;
        __syncthreads();
        sm[t] += a;
        __syncthreads();
    }
    if (i < n) {
        int excl = sm[t] - v + bsum[blockIdx.x];
        off[i] = excl;
        cur[i] = excl;
    }
}

__global__ void scatter_kernel(const int* __restrict__ src, const int* __restrict__ dst,
                               int* __restrict__ cur, int* __restrict__ srcs, int E)
{
    int t = blockIdx.x * blockDim.x + threadIdx.x;
    if (t < E) {
        int p = atomicAdd(&cur[dst[t]], 1);
        srcs[p] = src[t];
    }
}

// ---------------------------------------------------------------------------
// Fused edge-softmax attention; q,v fp16 gathers (half traffic), k fp32.
// ---------------------------------------------------------------------------
__global__ void attn_kernel(const __half* __restrict__ qh, const float* __restrict__ k,
                            const __half* __restrict__ vh, const int* __restrict__ off,
                            const int* __restrict__ srcs, uint4* __restrict__ agg2, int n)
{
    int node = blockIdx.x * 8 + threadIdx.y;
    if (node >= n) return;
    int lane = threadIdx.x;

    float4 kf = *(const float4*)(k + (size_t)node * DDIM + lane * 4);
    int beg = off[node], end = off[node + 1];

    float m = -INFINITY, ssum = 0.f;
    float4 acc = make_float4(0.f, 0.f, 0.f, 0.f);

    auto cvt4 = [](uint2 r) {
        float2 f0 = __half22float2(*(__half2*)&r.x);
        float2 f1 = __half22float2(*(__half2*)&r.y);
        return make_float4(f0.x, f0.y, f1.x, f1.y);
    };

    if (beg < end) {
        int s0 = srcs[beg];
        uint2 qraw = ((const uint2*)(qh + (size_t)s0 * DDIM))[lane];
        uint2 vraw = ((const uint2*)(vh + (size_t)s0 * DDIM))[lane];
        for (int j = beg; j < end; j++) {
            float4 qc = cvt4(qraw), vc = cvt4(vraw);
            if (j + 1 < end) {
                int s = srcs[j + 1];
                qraw = ((const uint2*)(qh + (size_t)s * DDIM))[lane];
                vraw = ((const uint2*)(vh + (size_t)s * DDIM))[lane];
            }
            float p = qc.x * kf.x + qc.y * kf.y + qc.z * kf.z + qc.w * kf.w;
            p += __shfl_xor_sync(0xffffffffu, p, 1);
            p += __shfl_xor_sync(0xffffffffu, p, 2);
            p *= 0.25f;  // 1/sqrt(HD=16)

            float mn = fmaxf(m, p);
            float scale = __expf(m - mn);
            float w = __expf(p - mn);
            ssum = ssum * scale + w;

            acc.x = acc.x * scale + w * vc.x;
            acc.y = acc.y * scale + w * vc.y;
            acc.z = acc.z * scale + w * vc.z;
            acc.w = acc.w * scale + w * vc.w;
            m = mn;
        }
    }

    float inv = (end > beg) ? 1.f / ssum : 0.f;
    float4 o;
    o.x = acc.x * inv; o.y = acc.y * inv; o.z = acc.z * inv; o.w = acc.w * inv;
    agg2[(size_t)node * 32 + lane] = split4(o);
}

// ---------------------------------------------------------------------------
// Host orchestration
// ---------------------------------------------------------------------------
extern "C" void kernel_launch(void* const* d_in, const int* in_sizes, int n_in,
                              void* d_out, int out_size)
{
    const float* x    = (const float*)d_in[0];
    const int*   esrc = (const int*)  d_in[1];
    const int*   edst = (const int*)  d_in[2];
    const float* Wi   = (const float*)d_in[3];
    const float* bi   = (const float*)d_in[4];
    const float* Wq   = (const float*)d_in[5];
    const float* bq   = (const float*)d_in[6];
    const float* Wk   = (const float*)d_in[7];
    const float* bk   = (const float*)d_in[8];
    const float* Wv   = (const float*)d_in[9];
    const float* bv   = (const float*)d_in[10];
    const float* Wo   = (const float*)d_in[11];
    const float* bo   = (const float*)d_in[12];
    const float* g1   = (const float*)d_in[13];
    const float* b1   = (const float*)d_in[14];
    const float* Wf1  = (const float*)d_in[15];
    const float* bf1  = (const float*)d_in[16];
    const float* Wf2  = (const float*)d_in[17];
    const float* bf2  = (const float*)d_in[18];
    const float* gout = (const float*)d_in[19];
    const float* boutg= (const float*)d_in[20];
    const float* Wout = (const float*)d_in[21];
    const float* bout = (const float*)d_in[22];

    const int Nn = in_sizes[0] / FIN;   // 50000
    const int Ee = in_sizes[1];         // 800000

    float *h, *k;
    __half *qh, *vh;
    uint2 *x2, *ln2, *ag2, *ff2;
    uint4 *wp;
    int *deg, *cur, *off, *bsum, *srcs;
    cudaGetSymbolAddress((void**)&h,    g_h);
    cudaGetSymbolAddress((void**)&qh,   g_qh);
    cudaGetSymbolAddress((void**)&k,    g_k);
    cudaGetSymbolAddress((void**)&vh,   g_vh);
    cudaGetSymbolAddress((void**)&x2,   g_x2);
    cudaGetSymbolAddress((void**)&ln2,  g_ln2);
    cudaGetSymbolAddress((void**)&ag2,  g_ag2);
    cudaGetSymbolAddress((void**)&ff2,  g_ff2);
    cudaGetSymbolAddress((void**)&wp,   g_wp);
    cudaGetSymbolAddress((void**)&deg,  g_deg);
    cudaGetSymbolAddress((void**)&cur,  g_cur);
    cudaGetSymbolAddress((void**)&off,  g_off);
    cudaGetSymbolAddress((void**)&bsum, g_bsum);
    cudaGetSymbolAddress((void**)&srcs, g_srcs);

    cudaFuncSetAttribute(gemm_tc_kernel<true,  false, 0, 1>, cudaFuncAttributeMaxDynamicSharedMemorySize, GEMM_SMEM(1));
    cudaFuncSetAttribute(gemm_tc_kernel<false, true,  0, 1>, cudaFuncAttributeMaxDynamicSharedMemorySize, GEMM_SMEM(1));
    cudaFuncSetAttribute(gemm_tc_kernel<false, false, 0, 1>, cudaFuncAttributeMaxDynamicSharedMemorySize, GEMM_SMEM(1));
    cudaFuncSetAttribute(gemm_tc_kernel<true,  false, 1, 2>, cudaFuncAttributeMaxDynamicSharedMemorySize, GEMM_SMEM(2));
    cudaFuncSetAttribute(gemm_qkv_kernel,                    cudaFuncAttributeMaxDynamicSharedMemorySize, GEMM_SMEM(2));

    const int mb1 = (Nn + 63) / 64;
    const int mb2 = (Nn + 127) / 128;
    const dim3 gD(1, mb1);
    const dim3 gQKV(1, mb2, 3);
    const dim3 gF(2, mb2);
    const dim3 gC(1, mb1);
    const int lnBlocks = (Nn + 7) / 8;
    const dim3 warpRows(32, 8);
    const int eBlocks = (Ee + 255) / 256;
    const int nodeBlocks = (Nn + 7) / 8;
    const int nbScan = (Nn + 511) / 512;

    // ---- Prep (once per launch)
    {
        int n4 = Nn * FIN / 4;
        split_x_kernel<<<(n4 + 255) / 256, 256>>>(x, (uint4*)x2, n4);
        pack_all_kernel<<<(WP_TOTAL + 255) / 256, 256>>>(Wi, Wq, Wk, Wv, Wo, Wf1, Wf2, Wout, wp);
    }

    // ---- CSR build
    cudaMemsetAsync(deg, 0, Nn * sizeof(int));
    hist_kernel<<<eBlocks, 256>>>(edst, deg, Ee);
    scan_part_kernel<<<nbScan, 512>>>(deg, bsum, Nn);
    scan_top_kernel<<<1, 128>>>(bsum, off, Nn, nbScan);
    scan_apply_kernel<<<nbScan, 512>>>(deg, bsum, off, cur, Nn);
    scatter_kernel<<<eBlocks, 256>>>(esrc, edst, cur, srcs, Ee);

    // h = relu(x @ Wi + bi)
    gemm_tc_kernel<true, false, 0, 1><<<gD, 256, GEMM_SMEM(1)>>>(
        x2, wp + WP_WI, bi, nullptr, h, nullptr, Nn, DDIM, FIN);

    for (int i = 0; i < 5; i++) {
        const uint4* wl = wp + WP_L0 + (size_t)i * WP_LSTR;
        float* hOut = (i < 4) ? h : (float*)d_out;

        ln_kernel<<<lnBlocks, warpRows>>>(h, g1 + i * DDIM, b1 + i * DDIM, (uint4*)ln2, Nn);
        gemm_qkv_kernel<<<gQKV, 256, GEMM_SMEM(2)>>>(
            ln2, wl, bq + i * DDIM, bk + i * DDIM, bv + i * DDIM, qh, k, vh, Nn);

        attn_kernel<<<nodeBlocks, warpRows>>>(qh, k, vh, off, srcs, (uint4*)ag2, Nn);

        // h = h + agg @ Wo + bo   (bias, Rsd, C order)
        gemm_tc_kernel<false, true, 0, 1><<<gD, 256, GEMM_SMEM(1)>>>(
            ag2, wl + WPO_O, bo + i * DDIM, /*Rsd=*/h, /*C=*/h, nullptr, Nn, DDIM, DDIM);

        ln_kernel<<<lnBlocks, warpRows>>>(h, g1 + i * DDIM, b1 + i * DDIM, (uint4*)ln2, Nn);
        gemm_tc_kernel<true, false, 1, 2><<<gF, 256, GEMM_SMEM(2)>>>(
            ln2, wl + WPO_F1, bf1 + i * 2 * DDIM, nullptr, nullptr, ff2, Nn, 2 * DDIM, DDIM);

        // hOut = h + ff @ Wf2 + bf2
        gemm_tc_kernel<false, true, 0, 1><<<gD, 256, GEMM_SMEM(1)>>>(
            ff2, wl + WPO_F2, bf2 + i * DDIM, /*Rsd=*/h, /*C=*/hOut, nullptr, Nn, DDIM, 2 * DDIM);
    }

    // mid already sits in d_out[0 : Nn*DDIM]. Final LN reads it from there.
    ln_kernel<<<lnBlocks, warpRows>>>((const float*)d_out, gout, boutg, (uint4*)ln2, Nn);
    gemm_tc_kernel<false, false, 0, 1><<<gC, 256, GEMM_SMEM(1)>>>(
        ln2, wp + WP_WOUT, bout, nullptr, (float*)d_out + (size_t)Nn * DDIM, nullptr,
        Nn, NCLS, DDIM);
}

// round 15
// speedup vs baseline: 1.6521x; 1.0073x over previous
#include <cuda_runtime.h>
#include <cuda_bf16.h>
#include <cuda_fp16.h>
#include <math.h>
#include <stdint.h>

// ---------------------------------------------------------------------------
// Problem constants
// ---------------------------------------------------------------------------
#define NMAX 50000
#define EMAX 800000
#define DDIM 128
#define HEADS 8
#define FIN 256
#define NCLS 40

// Packed-weight arena (uint4 units). Per 128-col block of 16 k: 512 uint4.
#define WP_WI    0
#define WP_L0    8192
#define WPO_Q    0
#define WPO_K    4096
#define WPO_V    8192
#define WPO_O    12288
#define WPO_F1   16384
#define WPO_F2   24576
#define WP_LSTR  32768
#define WP_WOUT  (WP_L0 + 5 * WP_LSTR)
#define WP_TOTAL (WP_WOUT + 4096)

// ---------------------------------------------------------------------------
// Device scratch
// ---------------------------------------------------------------------------
__device__ float  g_h  [NMAX * DDIM];
__device__ __half g_qh [NMAX * DDIM];
__device__ float  g_k  [NMAX * DDIM];
__device__ __half g_vh [NMAX * DDIM];
__device__ uint2  g_x2 [NMAX * FIN / 2];
__device__ uint2  g_ln2[NMAX * DDIM / 2];
__device__ uint2  g_ag2[NMAX * DDIM / 2];
__device__ uint2  g_ff2[NMAX * DDIM];
__device__ uint4  g_wp [WP_TOTAL];
__device__ int    g_deg [NMAX];
__device__ int    g_cur [NMAX];
__device__ int    g_off [NMAX + 1];
__device__ int    g_bsum[256];
__device__ int    g_srcs[EMAX];

// ---------------------------------------------------------------------------
// Helpers
// ---------------------------------------------------------------------------
__device__ __forceinline__ unsigned pack_bf2(float a, float b)
{
    __nv_bfloat162 t = __floats2bfloat162_rn(a, b);
    return *reinterpret_cast<unsigned*>(&t);
}

__device__ __forceinline__ uint4 split4(float4 v)
{
    float h0 = __bfloat162float(__float2bfloat16_rn(v.x));
    float h1 = __bfloat162float(__float2bfloat16_rn(v.y));
    float h2 = __bfloat162float(__float2bfloat16_rn(v.z));
    float h3 = __bfloat162float(__float2bfloat16_rn(v.w));
    uint4 u;
    u.x = pack_bf2(h0, h1);
    u.y = pack_bf2(v.x - h0, v.y - h1);
    u.z = pack_bf2(h2, h3);
    u.w = pack_bf2(v.z - h2, v.w - h3);
    return u;
}

__device__ __forceinline__ void mma_bf16(float* d, const uint32_t* a, const uint32_t* b)
{
    asm volatile(
        "mma.sync.aligned.m16n8k16.row.col.f32.bf16.bf16.f32 "
        "{%0,%1,%2,%3}, {%4,%5,%6,%7}, {%8,%9}, {%0,%1,%2,%3};\n"
        : "+f"(d[0]), "+f"(d[1]), "+f"(d[2]), "+f"(d[3])
        : "r"(a[0]), "r"(a[1]), "r"(a[2]), "r"(a[3]), "r"(b[0]), "r"(b[1]));
}

__device__ __forceinline__ void cp_async16(uint32_t saddr, const void* gptr, bool pred)
{
    int bytes = pred ? 16 : 0;
    asm volatile("cp.async.cg.shared.global [%0], [%1], 16, %2;\n"
                 :: "r"(saddr), "l"(gptr), "r"(bytes));
}
#define CP_COMMIT() asm volatile("cp.async.commit_group;\n" ::: "memory")
#define CP_WAIT0()  asm volatile("cp.async.wait_group 0;\n" ::: "memory")

// ---------------------------------------------------------------------------
// Prep: split x into interleaved bf16 pairs
// ---------------------------------------------------------------------------
__global__ void split_x_kernel(const float* __restrict__ src, uint4* __restrict__ dst, int n4)
{
    int t = blockIdx.x * blockDim.x + threadIdx.x;
    if (t >= n4) return;
    dst[t] = split4(((const float4*)src)[t]);
}

// ---------------------------------------------------------------------------
// Prep: pack ALL weights in ONE launch (arena offset == thread index)
// ---------------------------------------------------------------------------
__global__ void pack_all_kernel(
    const float* __restrict__ Wi,  const float* __restrict__ Wq,
    const float* __restrict__ Wk,  const float* __restrict__ Wv,
    const float* __restrict__ Wo,  const float* __restrict__ Wf1,
    const float* __restrict__ Wf2, const float* __restrict__ Wout,
    uint4* __restrict__ dst)
{
    int t = blockIdx.x * blockDim.x + threadIdx.x;
    if (t >= WP_TOTAL) return;

    const float* W;
    int K, Nact, li;
    if (t < WP_L0) {
        W = Wi; K = 256; Nact = 128; li = t;
    } else if (t < WP_WOUT) {
        int r = t - WP_L0;
        int layer = r / WP_LSTR;
        int o = r % WP_LSTR;
        if (o < WPO_F1) {
            int which = o >> 12;
            li = o & 4095;
            K = 128; Nact = 128;
            const float* base = (which == 0) ? Wq : (which == 1) ? Wk
                              : (which == 2) ? Wv : Wo;
            W = base + (size_t)layer * 16384;
        } else if (o < WPO_F2) {
            li = o - WPO_F1; K = 128; Nact = 256;
            W = Wf1 + (size_t)layer * 32768;
        } else {
            li = o - WPO_F2; K = 256; Nact = 128;
            W = Wf2 + (size_t)layer * 32768;
        }
    } else {
        W = Wout; K = 128; Nact = 40; li = t - WP_WOUT;
    }

    int c   = li & 3;
    int na  = li >> 2;
    int nl  = na & 127;
    int blk = na >> 7;
    int kb  = blk % (K >> 4);
    int nbk = blk / (K >> 4);
    int n   = nbk * 128 + nl;
    int k0  = kb * 16 + 2 * c;

    float va = 0.f, vb = 0.f, vc = 0.f, vd = 0.f;
    if (n < Nact) {
        va = W[(size_t)(k0 + 0) * Nact + n];
        vb = W[(size_t)(k0 + 1) * Nact + n];
        vc = W[(size_t)(k0 + 8) * Nact + n];
        vd = W[(size_t)(k0 + 9) * Nact + n];
    }
    float ha = __bfloat162float(__float2bfloat16_rn(va));
    float hb = __bfloat162float(__float2bfloat16_rn(vb));
    float hc = __bfloat162float(__float2bfloat16_rn(vc));
    float hd = __bfloat162float(__float2bfloat16_rn(vd));
    uint4 u;
    u.x = pack_bf2(ha, hb);
    u.y = pack_bf2(hc, hd);
    u.z = pack_bf2(va - ha, vb - hb);
    u.w = pack_bf2(vc - hc, vd - hd);
    dst[t] = u;
}

// ---------------------------------------------------------------------------
// BF16 3-term tensor-core GEMM, cp.async 2-stage double buffer, BK=32 (R12 core).
// MT: 2 -> 128-row block (warp tile 32x64), 1 -> 64-row block (16x64).
// OUTM: 0 = fp32, 1 = bf16-pair (C2), 2 = fp16 (C reinterpreted as __half*).
// ---------------------------------------------------------------------------
#define BK 32
#define A_STB 160
#define GEMM_SMEM(MT) (2 * ((MT) * 64 * A_STB + 16384))

template <bool RELU, bool RES, int OUTM, int MT>
__device__ __forceinline__ void gemm_tc_body(
    const uint2* __restrict__ Ap, const uint4* __restrict__ Bp,
    const float* __restrict__ bias, const float* __restrict__ Rsd,
    float* __restrict__ C, uint2* __restrict__ C2,
    int M, int N, int K)
{
    extern __shared__ __align__(16) char smc[];

    constexpr int ROWS  = MT * 64;
    constexpr int SBOFF = ROWS * A_STB;
    constexpr int STB   = SBOFF + 16384;

    const int tid  = threadIdx.x;
    const int lane = tid & 31;
    const int wid  = tid >> 5;
    const int g    = lane >> 2;
    const int c    = lane & 3;
    const int wm   = (wid >> 1) * (MT * 16);
    const int wn   = (wid & 1) * 64;

    const int row0 = blockIdx.y * ROWS;
    const int col0 = blockIdx.x * 128;

    const char* Bbase = (const char*)(Bp + (size_t)blockIdx.x * (K >> 4) * 512);
    const uint32_t smBase = (uint32_t)__cvta_generic_to_shared(smc);

    auto loadTile = [&](int st, int kt) {
        uint32_t sb = smBase + st * STB;
        #pragma unroll
        for (int i = 0; i < ROWS / 32; i++) {
            int id = tid + i * 256;
            int r  = id >> 3;
            int ch = id & 7;
            int ar = row0 + r;
            bool ok = ar < M;
            const char* gp = (const char*)Ap
                + ((size_t)(ok ? ar : 0) * (K >> 1) + (size_t)kt * (BK >> 1)) * 8 + ch * 16;
            cp_async16(sb + r * A_STB + ch * 16, gp, ok);
        }
        const char* bp = Bbase + (size_t)kt * 16384;
        #pragma unroll
        for (int i = 0; i < 4; i++) {
            int id = tid + i * 256;
            cp_async16(sb + SBOFF + id * 16, bp + id * 16, true);
        }
    };

    float acc[MT][8][4] = {};

    const int KT = K / BK;
    loadTile(0, 0);
    CP_COMMIT();

    for (int kt = 0; kt < KT; kt++) {
        CP_WAIT0();
        __syncthreads();
        if (kt + 1 < KT) {
            loadTile((kt + 1) & 1, kt + 1);
            CP_COMMIT();
        }

        const char* S = smc + (kt & 1) * STB;

        #pragma unroll
        for (int kk = 0; kk < 2; kk++) {
            uint32_t aH[MT][4], aL[MT][4];
            #pragma unroll
            for (int t = 0; t < MT; t++) {
                const char* base = S + (wm + 16 * t + g) * A_STB;
                uint2 w0 = *(const uint2*)(base + (kk * 8 + c) * 8);
                uint2 w1 = *(const uint2*)(base + 8 * A_STB + (kk * 8 + c) * 8);
                uint2 w2 = *(const uint2*)(base + (kk * 8 + c + 4) * 8);
                uint2 w3 = *(const uint2*)(base + 8 * A_STB + (kk * 8 + c + 4) * 8);
                aH[t][0] = w0.x; aL[t][0] = w0.y;
                aH[t][1] = w1.x; aL[t][1] = w1.y;
                aH[t][2] = w2.x; aL[t][2] = w2.y;
                aH[t][3] = w3.x; aL[t][3] = w3.y;
            }
            #pragma unroll
            for (int j = 0; j < 8; j++) {
                int n = wn + 8 * j + g;
                uint4 bb = *(const uint4*)(S + SBOFF + kk * 8192 + (n * 4 + c) * 16);
                uint32_t bH[2] = {bb.x, bb.y};
                uint32_t bL[2] = {bb.z, bb.w};
                #pragma unroll
                for (int t = 0; t < MT; t++) {
                    float* d = acc[t][j];
                    mma_bf16(d, aH[t], bH);
                    mma_bf16(d, aL[t], bH);
                    mma_bf16(d, aH[t], bL);
                }
            }
        }
        __syncthreads();
    }

    // ---- Epilogue: thread owns rows {wm+16t+g, +8}, cols {wn+8j+2c, +1}
    #pragma unroll
    for (int t = 0; t < MT; t++) {
        #pragma unroll
        for (int rr = 0; rr < 2; rr++) {
            int r = row0 + wm + 16 * t + g + rr * 8;
            if (r >= M) continue;
            #pragma unroll
            for (int j = 0; j < 8; j++) {
                int cc = col0 + wn + 8 * j + 2 * c;
                if (cc >= N) continue;
                float v0 = acc[t][j][rr * 2 + 0] + bias[cc];
                float v1 = acc[t][j][rr * 2 + 1] + bias[cc + 1];
                if (RELU) { v0 = fmaxf(v0, 0.f); v1 = fmaxf(v1, 0.f); }
                if (RES) {
                    float2 rv = *(const float2*)(Rsd + (size_t)r * N + cc);
                    v0 += rv.x; v1 += rv.y;
                }
                if (OUTM == 1) {
                    float h0 = __bfloat162float(__float2bfloat16_rn(v0));
                    float h1 = __bfloat162float(__float2bfloat16_rn(v1));
                    uint2 u;
                    u.x = pack_bf2(h0, h1);
                    u.y = pack_bf2(v0 - h0, v1 - h1);
                    C2[(size_t)r * (N >> 1) + (cc >> 1)] = u;
                } else if (OUTM == 2) {
                    __half2 hv = __floats2half2_rn(v0, v1);
                    *(__half2*)((__half*)C + (size_t)r * N + cc) = hv;
                } else {
                    float2 out; out.x = v0; out.y = v1;
                    *(float2*)(C + (size_t)r * N + cc) = out;
                }
            }
        }
    }
}

template <bool RELU, bool RES, int OUTM, int MT>
__global__ __launch_bounds__(256, 2) void gemm_tc_kernel(
    const uint2* __restrict__ Ap, const uint4* __restrict__ Bp,
    const float* __restrict__ bias, const float* __restrict__ Rsd,
    float* __restrict__ C, uint2* __restrict__ C2, int M, int N, int K)
{
    gemm_tc_body<RELU, RES, OUTM, MT>(Ap, Bp, bias, Rsd, C, C2, M, N, K);
}

// q,v written as fp16; k as fp32
__global__ __launch_bounds__(256, 2) void gemm_qkv_kernel(
    const uint2* __restrict__ Ap, const uint4* __restrict__ wp,
    const float* __restrict__ bq, const float* __restrict__ bk, const float* __restrict__ bv,
    __half* __restrict__ qh, float* __restrict__ k, __half* __restrict__ vh, int M)
{
    if (blockIdx.z == 0)
        gemm_tc_body<false, false, 2, 2>(Ap, wp + WPO_Q, bq, nullptr, (float*)qh, nullptr, M, DDIM, DDIM);
    else if (blockIdx.z == 1)
        gemm_tc_body<false, false, 0, 2>(Ap, wp + WPO_K, bk, nullptr, k, nullptr, M, DDIM, DDIM);
    else
        gemm_tc_body<false, false, 2, 2>(Ap, wp + WPO_V, bv, nullptr, (float*)vh, nullptr, M, DDIM, DDIM);
}

// ---------------------------------------------------------------------------
// LayerNorm over D=128 -> interleaved bf16 pair output
// ---------------------------------------------------------------------------
__global__ void ln_kernel(const float* __restrict__ X, const float* __restrict__ g,
                          const float* __restrict__ b, uint4* __restrict__ Y2, int n)
{
    int row = blockIdx.x * 8 + threadIdx.y;
    if (row >= n) return;
    int lane = threadIdx.x;
    float4 x = *(const float4*)(X + (size_t)row * DDIM + lane * 4);
    float s  = x.x + x.y + x.z + x.w;
    float ss = x.x * x.x + x.y * x.y + x.z * x.z + x.w * x.w;
    #pragma unroll
    for (int o = 16; o > 0; o >>= 1) {
        s  += __shfl_xor_sync(0xffffffffu, s, o);
        ss += __shfl_xor_sync(0xffffffffu, ss, o);
    }
    float mu  = s * (1.f / DDIM);
    float var = ss * (1.f / DDIM) - mu * mu;
    float rstd = rsqrtf(var + 1e-5f);
    float4 gv = *(const float4*)(g + lane * 4);
    float4 bv = *(const float4*)(b + lane * 4);
    float4 y;
    y.x = (x.x - mu) * rstd * gv.x + bv.x;
    y.y = (x.y - mu) * rstd * gv.y + bv.y;
    y.z = (x.z - mu) * rstd * gv.z + bv.z;
    y.w = (x.w - mu) * rstd * gv.w + bv.w;
    Y2[(size_t)row * 32 + lane] = split4(y);
}

// ---------------------------------------------------------------------------
// CSR build: histogram + 3-phase scan + scatter
// ---------------------------------------------------------------------------
__global__ void hist_kernel(const int* __restrict__ dst, int* __restrict__ deg, int E)
{
    int t = blockIdx.x * blockDim.x + threadIdx.x;
    if (t < E) atomicAdd(&deg[dst[t]], 1);
}

__global__ void scan_part_kernel(const int* __restrict__ deg, int* __restrict__ bsum, int n)
{
    __shared__ int ws[16];
    int t = threadIdx.x;
    int i = blockIdx.x * 512 + t;
    int v = (i < n) ? deg[i] : 0;
    #pragma unroll
    for (int o = 16; o > 0; o >>= 1) v += __shfl_xor_sync(0xffffffffu, v, o);
    if ((t & 31) == 0) ws[t >> 5] = v;
    __syncthreads();
    if (t == 0) {
        int s = 0;
        #pragma unroll
        for (int w = 0; w < 16; w++) s += ws[w];
        bsum[blockIdx.x] = s;
    }
}

__global__ void scan_top_kernel(int* __restrict__ bsum, int* __restrict__ off, int n, int nb)
{
    __shared__ int sm[128];
    int t = threadIdx.x;
    int v = (t < nb) ? bsum[t] : 0;
    sm[t] = v;
    __syncthreads();
    #pragma unroll
    for (int o = 1; o < 128; o <<= 1) {
        int a = (t >= o) ? sm[t - o] : 0;
        __syncthreads();
        sm[t] += a;
        __syncthreads();
    }
    if (t < nb) bsum[t] = sm[t] - v;
    if (t == 0) off[n] = sm[nb - 1];
}

__global__ void scan_apply_kernel(const int* __restrict__ deg, const int* __restrict__ bsum,
                                  int* __restrict__ off, int* __restrict__ cur, int n)
{
    __shared__ int sm[512];
    int t = threadIdx.x;
    int i = blockIdx.x * 512 + t;
    int v = (i < n) ? deg[i] : 0;
    sm[t] = v;
    __syncthreads();
    #pragma unroll
    for (int o = 1; o < 512; o <<= 1) {
        int a = (t >= o) ? sm[t - o] : 0;
        __syncthreads();
        sm[t] += a;
        __syncthreads();
    }
    if (i < n) {
        int excl = sm[t] - v + bsum[blockIdx.x];
        off[i] = excl;
        cur[i] = excl;
    }
}

__global__ void scatter_kernel(const int* __restrict__ src, const int* __restrict__ dst,
                               int* __restrict__ cur, int* __restrict__ srcs, int E)
{
    int t = blockIdx.x * blockDim.x + threadIdx.x;
    if (t < E) {
        int p = atomicAdd(&cur[dst[t]], 1);
        srcs[p] = src[t];
    }
}

// ---------------------------------------------------------------------------
// Fused edge-softmax attention; q,v fp16 gathers; ONE warp per CTA so warps
// retire independently (degree imbalance no longer holds CTA slots).
// ---------------------------------------------------------------------------
__global__ __launch_bounds__(32) void attn_kernel(
    const __half* __restrict__ qh, const float* __restrict__ k,
    const __half* __restrict__ vh, const int* __restrict__ off,
    const int* __restrict__ srcs, uint4* __restrict__ agg2, int n)
{
    int node = blockIdx.x;
    if (node >= n) return;
    int lane = threadIdx.x;

    float4 kf = *(const float4*)(k + (size_t)node * DDIM + lane * 4);
    int beg = off[node], end = off[node + 1];

    float m = -INFINITY, ssum = 0.f;
    float4 acc = make_float4(0.f, 0.f, 0.f, 0.f);

    auto cvt4 = [](uint2 r) {
        float2 f0 = __half22float2(*(__half2*)&r.x);
        float2 f1 = __half22float2(*(__half2*)&r.y);
        return make_float4(f0.x, f0.y, f1.x, f1.y);
    };

    if (beg < end) {
        int s0 = srcs[beg];
        uint2 qraw = ((const uint2*)(qh + (size_t)s0 * DDIM))[lane];
        uint2 vraw = ((const uint2*)(vh + (size_t)s0 * DDIM))[lane];
        for (int j = beg; j < end; j++) {
            float4 qc = cvt4(qraw), vc = cvt4(vraw);
            if (j + 1 < end) {
                int s = srcs[j + 1];
                qraw = ((const uint2*)(qh + (size_t)s * DDIM))[lane];
                vraw = ((const uint2*)(vh + (size_t)s * DDIM))[lane];
            }
            float p = qc.x * kf.x + qc.y * kf.y + qc.z * kf.z + qc.w * kf.w;
            p += __shfl_xor_sync(0xffffffffu, p, 1);
            p += __shfl_xor_sync(0xffffffffu, p, 2);
            p *= 0.25f;  // 1/sqrt(HD=16)

            float mn = fmaxf(m, p);
            float scale = __expf(m - mn);
            float w = __expf(p - mn);
            ssum = ssum * scale + w;

            acc.x = acc.x * scale + w * vc.x;
            acc.y = acc.y * scale + w * vc.y;
            acc.z = acc.z * scale + w * vc.z;
            acc.w = acc.w * scale + w * vc.w;
            m = mn;
        }
    }

    float inv = (end > beg) ? 1.f / ssum : 0.f;
    float4 o;
    o.x = acc.x * inv; o.y = acc.y * inv; o.z = acc.z * inv; o.w = acc.w * inv;
    agg2[(size_t)node * 32 + lane] = split4(o);
}

// ---------------------------------------------------------------------------
// Host orchestration
// ---------------------------------------------------------------------------
extern "C" void kernel_launch(void* const* d_in, const int* in_sizes, int n_in,
                              void* d_out, int out_size)
{
    const float* x    = (const float*)d_in[0];
    const int*   esrc = (const int*)  d_in[1];
    const int*   edst = (const int*)  d_in[2];
    const float* Wi   = (const float*)d_in[3];
    const float* bi   = (const float*)d_in[4];
    const float* Wq   = (const float*)d_in[5];
    const float* bq   = (const float*)d_in[6];
    const float* Wk   = (const float*)d_in[7];
    const float* bk   = (const float*)d_in[8];
    const float* Wv   = (const float*)d_in[9];
    const float* bv   = (const float*)d_in[10];
    const float* Wo   = (const float*)d_in[11];
    const float* bo   = (const float*)d_in[12];
    const float* g1   = (const float*)d_in[13];
    const float* b1   = (const float*)d_in[14];
    const float* Wf1  = (const float*)d_in[15];
    const float* bf1  = (const float*)d_in[16];
    const float* Wf2  = (const float*)d_in[17];
    const float* bf2  = (const float*)d_in[18];
    const float* gout = (const float*)d_in[19];
    const float* boutg= (const float*)d_in[20];
    const float* Wout = (const float*)d_in[21];
    const float* bout = (const float*)d_in[22];

    const int Nn = in_sizes[0] / FIN;   // 50000
    const int Ee = in_sizes[1];         // 800000

    float *h, *k;
    __half *qh, *vh;
    uint2 *x2, *ln2, *ag2, *ff2;
    uint4 *wp;
    int *deg, *cur, *off, *bsum, *srcs;
    cudaGetSymbolAddress((void**)&h,    g_h);
    cudaGetSymbolAddress((void**)&qh,   g_qh);
    cudaGetSymbolAddress((void**)&k,    g_k);
    cudaGetSymbolAddress((void**)&vh,   g_vh);
    cudaGetSymbolAddress((void**)&x2,   g_x2);
    cudaGetSymbolAddress((void**)&ln2,  g_ln2);
    cudaGetSymbolAddress((void**)&ag2,  g_ag2);
    cudaGetSymbolAddress((void**)&ff2,  g_ff2);
    cudaGetSymbolAddress((void**)&wp,   g_wp);
    cudaGetSymbolAddress((void**)&deg,  g_deg);
    cudaGetSymbolAddress((void**)&cur,  g_cur);
    cudaGetSymbolAddress((void**)&off,  g_off);
    cudaGetSymbolAddress((void**)&bsum, g_bsum);
    cudaGetSymbolAddress((void**)&srcs, g_srcs);

    cudaFuncSetAttribute(gemm_tc_kernel<true,  false, 0, 1>, cudaFuncAttributeMaxDynamicSharedMemorySize, GEMM_SMEM(1));
    cudaFuncSetAttribute(gemm_tc_kernel<false, true,  0, 1>, cudaFuncAttributeMaxDynamicSharedMemorySize, GEMM_SMEM(1));
    cudaFuncSetAttribute(gemm_tc_kernel<false, false, 0, 1>, cudaFuncAttributeMaxDynamicSharedMemorySize, GEMM_SMEM(1));
    cudaFuncSetAttribute(gemm_tc_kernel<true,  false, 1, 2>, cudaFuncAttributeMaxDynamicSharedMemorySize, GEMM_SMEM(2));
    cudaFuncSetAttribute(gemm_qkv_kernel,                    cudaFuncAttributeMaxDynamicSharedMemorySize, GEMM_SMEM(2));

    const int mb1 = (Nn + 63) / 64;
    const int mb2 = (Nn + 127) / 128;
    const dim3 gD(1, mb1);
    const dim3 gQKV(1, mb2, 3);
    const dim3 gF(2, mb2);
    const dim3 gC(1, mb1);
    const int lnBlocks = (Nn + 7) / 8;
    const dim3 warpRows(32, 8);
    const int eBlocks = (Ee + 255) / 256;
    const int nbScan = (Nn + 511) / 512;

    // ---- Prep (once per launch)
    {
        int n4 = Nn * FIN / 4;
        split_x_kernel<<<(n4 + 255) / 256, 256>>>(x, (uint4*)x2, n4);
        pack_all_kernel<<<(WP_TOTAL + 255) / 256, 256>>>(Wi, Wq, Wk, Wv, Wo, Wf1, Wf2, Wout, wp);
    }

    // ---- CSR build
    cudaMemsetAsync(deg, 0, Nn * sizeof(int));
    hist_kernel<<<eBlocks, 256>>>(edst, deg, Ee);
    scan_part_kernel<<<nbScan, 512>>>(deg, bsum, Nn);
    scan_top_kernel<<<1, 128>>>(bsum, off, Nn, nbScan);
    scan_apply_kernel<<<nbScan, 512>>>(deg, bsum, off, cur, Nn);
    scatter_kernel<<<eBlocks, 256>>>(esrc, edst, cur, srcs, Ee);

    // h = relu(x @ Wi + bi)
    gemm_tc_kernel<true, false, 0, 1><<<gD, 256, GEMM_SMEM(1)>>>(
        x2, wp + WP_WI, bi, nullptr, h, nullptr, Nn, DDIM, FIN);

    for (int i = 0; i < 5; i++) {
        const uint4* wl = wp + WP_L0 + (size_t)i * WP_LSTR;
        float* hOut = (i < 4) ? h : (float*)d_out;

        ln_kernel<<<lnBlocks, warpRows>>>(h, g1 + i * DDIM, b1 + i * DDIM, (uint4*)ln2, Nn);
        gemm_qkv_kernel<<<gQKV, 256, GEMM_SMEM(2)>>>(
            ln2, wl, bq + i * DDIM, bk + i * DDIM, bv + i * DDIM, qh, k, vh, Nn);

        attn_kernel<<<Nn, 32>>>(qh, k, vh, off, srcs, (uint4*)ag2, Nn);

        // h = h + agg @ Wo + bo   (bias, Rsd, C order)
        gemm_tc_kernel<false, true, 0, 1><<<gD, 256, GEMM_SMEM(1)>>>(
            ag2, wl + WPO_O, bo + i * DDIM, /*Rsd=*/h, /*C=*/h, nullptr, Nn, DDIM, DDIM);

        ln_kernel<<<lnBlocks, warpRows>>>(h, g1 + i * DDIM, b1 + i * DDIM, (uint4*)ln2, Nn);
        gemm_tc_kernel<true, false, 1, 2><<<gF, 256, GEMM_SMEM(2)>>>(
            ln2, wl + WPO_F1, bf1 + i * 2 * DDIM, nullptr, nullptr, ff2, Nn, 2 * DDIM, DDIM);

        // hOut = h + ff @ Wf2 + bf2
        gemm_tc_kernel<false, true, 0, 1><<<gD, 256, GEMM_SMEM(1)>>>(
            ff2, wl + WPO_F2, bf2 + i * DDIM, /*Rsd=*/h, /*C=*/hOut, nullptr, Nn, DDIM, 2 * DDIM);
    }

    // mid already sits in d_out[0 : Nn*DDIM]. Final LN reads it from there.
    ln_kernel<<<lnBlocks, warpRows>>>((const float*)d_out, gout, boutg, (uint4*)ln2, Nn);
    gemm_tc_kernel<false, false, 0, 1><<<gC, 256, GEMM_SMEM(1)>>>(
        ln2, wp + WP_WOUT, bout, nullptr, (float*)d_out + (size_t)Nn * DDIM, nullptr,
        Nn, NCLS, DDIM);
}